// round 1
// baseline (speedup 1.0000x reference)
#include <cuda_runtime.h>
#include <math.h>

// Problem constants
#define BATCH 16
#define DQ    768
#define NQ    1024      // T*Hp*Wp = 4*16*16
#define NT    64
#define DKV   384
#define NH    12
#define HD    64
#define NKV   (BATCH*NT)      // 1024
#define DKV2  (2*DQ)          // 1536

// -log2(10000)/32  (rope inv_freq exponent step, hd=64)
#define NEG_L2B_32 (-0.41524101186091903f)

// ---------------------------------------------------------------------------
// Scratch (device globals — no allocation allowed)
// ---------------------------------------------------------------------------
__device__ float g_q[(size_t)BATCH*NQ*DQ];     // q after Wq (raw, pre-RoPE) [B, Nq, Dq]
__device__ float g_oT[(size_t)BATCH*DQ*NQ];    // attention output, TRANSPOSED [B, Dq, Nq]
__device__ float g_kv[(size_t)NKV*DKV2];       // raw kv = tokens@Wkv  [B*Nt, 1536]
__device__ float g_tokT[(size_t)DKV*NKV];      // tokens transposed [Dkv, B*Nt]

// ---------------------------------------------------------------------------
// tokens [NKV, DKV] -> g_tokT [DKV, NKV]
// ---------------------------------------------------------------------------
__global__ void __launch_bounds__(256)
transpose_tok(const float* __restrict__ tok)
{
    __shared__ float tile[32][33];
    int x = blockIdx.x * 32 + threadIdx.x;   // col in tok (DKV)
    int y = blockIdx.y * 32 + threadIdx.y;   // row in tok (NKV)
    #pragma unroll
    for (int i = 0; i < 32; i += 8)
        tile[threadIdx.y + i][threadIdx.x] = tok[(size_t)(y + i) * DKV + x];
    __syncthreads();
    int x2 = blockIdx.y * 32 + threadIdx.x;  // col in tokT (NKV)
    int y2 = blockIdx.x * 32 + threadIdx.y;  // row in tokT (DKV)
    #pragma unroll
    for (int i = 0; i < 32; i += 8)
        g_tokT[(size_t)(y2 + i) * NKV + x2] = tile[threadIdx.x][threadIdx.y + i];
}

// ---------------------------------------------------------------------------
// Generic SGEMM:  C[m, n] = sum_k A[k, m] * B[k, n]
// A given K-major ([K, M], leading dim lda), B row-major ([K, N], ldb).
// 128x128 tile, BK=8, 256 threads, 8x8 per thread (quadrant mapping),
// single-stage register prefetch.
// ---------------------------------------------------------------------------
__global__ void __launch_bounds__(256)
sgemm_kmajA(const float* __restrict__ A, const float* __restrict__ Bm,
            float* __restrict__ C,
            int lda, int ldb, int ldc, int K,
            int strideA, int strideB, int strideC)
{
    __shared__ float As[8][128];
    __shared__ float Bs[8][128];
    const int tid = threadIdx.x;
    const int tx = tid & 15;
    const int ty = tid >> 4;
    const int m0 = blockIdx.y * 128;
    const int n0 = blockIdx.x * 128;
    const float* Ab = A  + (size_t)blockIdx.z * strideA;
    const float* Bb = Bm + (size_t)blockIdx.z * strideB;
    float*       Cb = C  + (size_t)blockIdx.z * strideC;

    float acc[8][8];
    #pragma unroll
    for (int i = 0; i < 8; i++)
        #pragma unroll
        for (int j = 0; j < 8; j++) acc[i][j] = 0.f;

    // prologue: tile 0
    #pragma unroll
    for (int i = 0; i < 4; i++) {
        int idx = tid + i * 256;
        int kk = idx >> 7, mm = idx & 127;
        As[kk][mm] = Ab[(size_t)kk * lda + m0 + mm];
        Bs[kk][mm] = Bb[(size_t)kk * ldb + n0 + mm];
    }
    __syncthreads();

    const int nIter = K >> 3;
    for (int it = 0; it < nIter; it++) {
        float ra[4], rb[4];
        const bool has_next = (it + 1 < nIter);
        if (has_next) {
            int kbase = (it + 1) << 3;
            #pragma unroll
            for (int i = 0; i < 4; i++) {
                int idx = tid + i * 256;
                int kk = idx >> 7, mm = idx & 127;
                ra[i] = Ab[(size_t)(kbase + kk) * lda + m0 + mm];
                rb[i] = Bb[(size_t)(kbase + kk) * ldb + n0 + mm];
            }
        }
        #pragma unroll
        for (int kk = 0; kk < 8; kk++) {
            float4 a0 = *(const float4*)&As[kk][ty * 4];
            float4 a1 = *(const float4*)&As[kk][64 + ty * 4];
            float4 b0 = *(const float4*)&Bs[kk][tx * 4];
            float4 b1 = *(const float4*)&Bs[kk][64 + tx * 4];
            float av[8] = {a0.x, a0.y, a0.z, a0.w, a1.x, a1.y, a1.z, a1.w};
            float bv[8] = {b0.x, b0.y, b0.z, b0.w, b1.x, b1.y, b1.z, b1.w};
            #pragma unroll
            for (int i = 0; i < 8; i++)
                #pragma unroll
                for (int j = 0; j < 8; j++)
                    acc[i][j] += av[i] * bv[j];
        }
        __syncthreads();
        if (has_next) {
            #pragma unroll
            for (int i = 0; i < 4; i++) {
                int idx = tid + i * 256;
                int kk = idx >> 7, mm = idx & 127;
                As[kk][mm] = ra[i];
                Bs[kk][mm] = rb[i];
            }
        }
        __syncthreads();
    }

    #pragma unroll
    for (int i = 0; i < 8; i++) {
        int m = m0 + ((i < 4) ? (ty * 4 + i) : (64 + ty * 4 + i - 4));
        float4 v0 = make_float4(acc[i][0], acc[i][1], acc[i][2], acc[i][3]);
        float4 v1 = make_float4(acc[i][4], acc[i][5], acc[i][6], acc[i][7]);
        *(float4*)&Cb[(size_t)m * ldc + n0 + tx * 4]      = v0;
        *(float4*)&Cb[(size_t)m * ldc + n0 + 64 + tx * 4] = v1;
    }
}

// ---------------------------------------------------------------------------
// Output GEMM with fused epilogue:
//   out[b, d, n] = feat[b, d, n] + bout[d] + sum_j g_oT[b, j, n] * Wout[j, d]
// rows = d (from Wout cols), cols = n. A[k=j, m=d] = Wout[j*DQ + d] (K-major),
// B[k=j, n] = g_oT[b, j*NQ + n].
// ---------------------------------------------------------------------------
__global__ void __launch_bounds__(256)
sgemm_out(const float* __restrict__ Wout, const float* __restrict__ bout,
          const float* __restrict__ feat, float* __restrict__ outp)
{
    __shared__ float As[8][128];
    __shared__ float Bs[8][128];
    const int tid = threadIdx.x;
    const int tx = tid & 15;
    const int ty = tid >> 4;
    const int m0 = blockIdx.y * 128;     // d
    const int n0 = blockIdx.x * 128;     // n
    const int b  = blockIdx.z;
    const float* Bb = g_oT + (size_t)b * DQ * NQ;

    float acc[8][8];
    #pragma unroll
    for (int i = 0; i < 8; i++)
        #pragma unroll
        for (int j = 0; j < 8; j++) acc[i][j] = 0.f;

    #pragma unroll
    for (int i = 0; i < 4; i++) {
        int idx = tid + i * 256;
        int kk = idx >> 7, mm = idx & 127;
        As[kk][mm] = Wout[(size_t)kk * DQ + m0 + mm];
        Bs[kk][mm] = Bb[(size_t)kk * NQ + n0 + mm];
    }
    __syncthreads();

    const int nIter = DQ >> 3;
    for (int it = 0; it < nIter; it++) {
        float ra[4], rb[4];
        const bool has_next = (it + 1 < nIter);
        if (has_next) {
            int kbase = (it + 1) << 3;
            #pragma unroll
            for (int i = 0; i < 4; i++) {
                int idx = tid + i * 256;
                int kk = idx >> 7, mm = idx & 127;
                ra[i] = Wout[(size_t)(kbase + kk) * DQ + m0 + mm];
                rb[i] = Bb[(size_t)(kbase + kk) * NQ + n0 + mm];
            }
        }
        #pragma unroll
        for (int kk = 0; kk < 8; kk++) {
            float4 a0 = *(const float4*)&As[kk][ty * 4];
            float4 a1 = *(const float4*)&As[kk][64 + ty * 4];
            float4 b0 = *(const float4*)&Bs[kk][tx * 4];
            float4 b1 = *(const float4*)&Bs[kk][64 + tx * 4];
            float av[8] = {a0.x, a0.y, a0.z, a0.w, a1.x, a1.y, a1.z, a1.w};
            float bv[8] = {b0.x, b0.y, b0.z, b0.w, b1.x, b1.y, b1.z, b1.w};
            #pragma unroll
            for (int i = 0; i < 8; i++)
                #pragma unroll
                for (int j = 0; j < 8; j++)
                    acc[i][j] += av[i] * bv[j];
        }
        __syncthreads();
        if (has_next) {
            #pragma unroll
            for (int i = 0; i < 4; i++) {
                int idx = tid + i * 256;
                int kk = idx >> 7, mm = idx & 127;
                As[kk][mm] = ra[i];
                Bs[kk][mm] = rb[i];
            }
        }
        __syncthreads();
    }

    #pragma unroll
    for (int i = 0; i < 8; i++) {
        int d = m0 + ((i < 4) ? (ty * 4 + i) : (64 + ty * 4 + i - 4));
        float bias = bout[d];
        const float* frow = feat + ((size_t)b * DQ + d) * NQ + n0;
        float*       orow = outp + ((size_t)b * DQ + d) * NQ + n0;
        float4 f0 = *(const float4*)&frow[tx * 4];
        float4 f1 = *(const float4*)&frow[64 + tx * 4];
        float4 v0 = make_float4(acc[i][0] + f0.x + bias, acc[i][1] + f0.y + bias,
                                acc[i][2] + f0.z + bias, acc[i][3] + f0.w + bias);
        float4 v1 = make_float4(acc[i][4] + f1.x + bias, acc[i][5] + f1.y + bias,
                                acc[i][6] + f1.z + bias, acc[i][7] + f1.w + bias);
        *(float4*)&orow[tx * 4]      = v0;
        *(float4*)&orow[64 + tx * 4] = v1;
    }
}

// ---------------------------------------------------------------------------
// Attention: one thread per query row. K/V [64,64] staged in smem, RoPE
// applied to K in smem and to the q row in registers. Writes attention
// output TRANSPOSED into g_oT[b, h*64+j, n] for a coalesced output GEMM.
// grid (NQ/128, NH, BATCH), 128 threads.
// ---------------------------------------------------------------------------
__global__ void __launch_bounds__(128)
attn_kernel()
{
    const int r  = threadIdx.x;         // q row within tile
    const int qt = blockIdx.x;
    const int h  = blockIdx.y;
    const int b  = blockIdx.z;
    const int n  = qt * 128 + r;        // query position (rope index)

    __shared__ float sk[64][64];
    __shared__ float sv[64][64];

    // load raw K/V for this (b, h)
    const float* kvb = g_kv + (size_t)b * NT * DKV2 + h * HD;
    for (int idx = r; idx < NT * HD; idx += 128) {
        int t = idx >> 6, j = idx & 63;
        sk[t][j] = kvb[(size_t)t * DKV2 + j];
        sv[t][j] = kvb[(size_t)t * DKV2 + DQ + j];
    }
    __syncthreads();

    // RoPE on K, in place (pairs (i, i+32), position t)
    for (int idx = r; idx < NT * 32; idx += 128) {
        int t = idx >> 5, i = idx & 31;
        float inv = exp2f((float)i * NEG_L2B_32);
        float sn, cs;
        sincosf((float)t * inv, &sn, &cs);
        float x1 = sk[t][i], x2 = sk[t][i + 32];
        sk[t][i]      = x1 * cs - x2 * sn;
        sk[t][i + 32] = x2 * cs + x1 * sn;
    }
    __syncthreads();

    // load my q row (raw), apply RoPE in registers (position n)
    float raw[64], qr[64];
    const float* qrow = g_q + ((size_t)(b * NQ + n)) * DQ + h * HD;
    #pragma unroll
    for (int j4 = 0; j4 < 16; j4++) {
        float4 v = *(const float4*)&qrow[j4 * 4];
        raw[j4 * 4 + 0] = v.x; raw[j4 * 4 + 1] = v.y;
        raw[j4 * 4 + 2] = v.z; raw[j4 * 4 + 3] = v.w;
    }
    #pragma unroll
    for (int i = 0; i < 32; i++) {
        float inv = exp2f((float)i * NEG_L2B_32);
        float sn, cs;
        sincosf((float)n * inv, &sn, &cs);
        float x1 = raw[i], x2 = raw[i + 32];
        qr[i]      = x1 * cs - x2 * sn;
        qr[i + 32] = x2 * cs + x1 * sn;
    }

    // S = scale * qr . k_t
    float sreg[64];
    #pragma unroll
    for (int t = 0; t < 64; t++) {
        float ax = 0.f, ay = 0.f, az = 0.f, aw = 0.f;
        #pragma unroll
        for (int j4 = 0; j4 < 16; j4++) {
            float4 k4 = *(const float4*)&sk[t][j4 * 4];
            ax += qr[j4 * 4 + 0] * k4.x;
            ay += qr[j4 * 4 + 1] * k4.y;
            az += qr[j4 * 4 + 2] * k4.z;
            aw += qr[j4 * 4 + 3] * k4.w;
        }
        sreg[t] = 0.125f * ((ax + ay) + (az + aw));   // scale = hd^-0.5 = 1/8
    }

    // softmax over t
    float mx = sreg[0];
    #pragma unroll
    for (int t = 1; t < 64; t++) mx = fmaxf(mx, sreg[t]);
    float sum = 0.f;
    #pragma unroll
    for (int t = 0; t < 64; t++) { sreg[t] = expf(sreg[t] - mx); sum += sreg[t]; }
    float invs = 1.f / sum;

    // O = P @ V
    float o[64];
    #pragma unroll
    for (int j = 0; j < 64; j++) o[j] = 0.f;
    #pragma unroll
    for (int t = 0; t < 64; t++) {
        float p = sreg[t];
        #pragma unroll
        for (int j4 = 0; j4 < 16; j4++) {
            float4 v4 = *(const float4*)&sv[t][j4 * 4];
            o[j4 * 4 + 0] += p * v4.x;
            o[j4 * 4 + 1] += p * v4.y;
            o[j4 * 4 + 2] += p * v4.z;
            o[j4 * 4 + 3] += p * v4.w;
        }
    }

    // write transposed: g_oT[b, h*64+j, n]   (lanes -> consecutive n: coalesced)
    float* ob = g_oT + ((size_t)b * DQ + h * HD) * NQ + n;
    #pragma unroll
    for (int j = 0; j < 64; j++) ob[(size_t)j * NQ] = o[j] * invs;
}

// ---------------------------------------------------------------------------
// Launch
// ---------------------------------------------------------------------------
extern "C" void kernel_launch(void* const* d_in, const int* in_sizes, int n_in,
                              void* d_out, int out_size)
{
    (void)in_sizes; (void)n_in; (void)out_size;
    const float* feat   = (const float*)d_in[0];
    const float* tokens = (const float*)d_in[1];
    const float* Wq     = (const float*)d_in[2];
    const float* Wkv    = (const float*)d_in[3];
    const float* Wout   = (const float*)d_in[4];
    const float* bout   = (const float*)d_in[5];
    float* outp = (float*)d_out;

    float *pq, *pkv, *ptokT;
    cudaGetSymbolAddress((void**)&pq,    g_q);
    cudaGetSymbolAddress((void**)&pkv,   g_kv);
    cudaGetSymbolAddress((void**)&ptokT, g_tokT);

    // 1) tokens -> tokensT
    transpose_tok<<<dim3(DKV / 32, NKV / 32), dim3(32, 8)>>>(tokens);

    // 2) kv = tokens @ Wkv : C[r, c], M=NKV, N=DKV2, K=DKV
    sgemm_kmajA<<<dim3(DKV2 / 128, NKV / 128, 1), 256>>>(
        ptokT, Wkv, pkv, NKV, DKV2, DKV2, DKV, 0, 0, 0);

    // 3) q = feat^T @ Wq per batch : M=NQ, N=DQ, K=DQ
    sgemm_kmajA<<<dim3(DQ / 128, NQ / 128, BATCH), 256>>>(
        feat, Wq, pq, NQ, DQ, DQ, DQ, DQ * NQ, 0, NQ * DQ);

    // 4) attention (rope q/k, softmax, PV), writes g_oT
    attn_kernel<<<dim3(NQ / 128, NH, BATCH), 128>>>();

    // 5) out = feat + attnout @ Wout + bout, written [B, Dq, Nq]
    sgemm_out<<<dim3(NQ / 128, DQ / 128, BATCH), 256>>>(Wout, bout, feat, outp);
}

// round 3
// speedup vs baseline: 2.6129x; 2.6129x over previous
#include <cuda_runtime.h>
#include <cuda_bf16.h>
#include <math.h>

// Problem constants
#define BATCH 16
#define DQ    768
#define NQ    1024
#define NT    64
#define DKV   384
#define NH    12
#define HD    64
#define NKV   (BATCH*NT)
#define DKV2  (2*DQ)

#define NEG_L2B_32 (-0.41524101186091903f)   // -log2(10000)/32

// ---------------------------------------------------------------------------
// Scratch (device globals)
// ---------------------------------------------------------------------------
__device__ __align__(16) float g_q [(size_t)BATCH*NQ*DQ];   // q fp32 [B,Nq,Dq]
__device__ __align__(16) float g_kv[(size_t)NKV*DKV2];      // kv fp32 [B*Nt,1536]
__device__ __align__(16) unsigned short g_qin_h[(size_t)BATCH*NQ*DQ];
__device__ __align__(16) unsigned short g_qin_l[(size_t)BATCH*NQ*DQ];
__device__ __align__(16) unsigned short g_o_h [(size_t)BATCH*NQ*DQ];
__device__ __align__(16) unsigned short g_o_l [(size_t)BATCH*NQ*DQ];
__device__ __align__(16) unsigned short g_wqT_h[DQ*DQ],     g_wqT_l[DQ*DQ];
__device__ __align__(16) unsigned short g_wkvT_h[DKV2*DKV], g_wkvT_l[DKV2*DKV];
__device__ __align__(16) unsigned short g_woT_h[DQ*DQ],     g_woT_l[DQ*DQ];
__device__ __align__(16) unsigned short g_tok_h[NKV*DKV],   g_tok_l[NKV*DKV];

// ---------------------------------------------------------------------------
// Helpers (ALL base-ISA: sm_80-level mma.sync / ldmatrix / cp.async)
// ---------------------------------------------------------------------------
__device__ __forceinline__ unsigned smem_u32(const void* p) {
    unsigned a;
    asm("{ .reg .u64 t; cvta.to.shared.u64 t, %1; cvt.u32.u64 %0, t; }" : "=r"(a) : "l"(p));
    return a;
}
__device__ __forceinline__ unsigned swz(unsigned o) { return o ^ ((o >> 3) & 0x70); }

__device__ __forceinline__ void cpa16(unsigned s, const void* g) {
    asm volatile("cp.async.cg.shared.global [%0], [%1], 16;" :: "r"(s), "l"(g) : "memory");
}
#define CP_COMMIT() asm volatile("cp.async.commit_group;" ::: "memory")
#define CP_WAIT(n)  asm volatile("cp.async.wait_group %0;" :: "n"(n) : "memory")

__device__ __forceinline__ void ldsm4(unsigned* r, unsigned a) {
    asm volatile("ldmatrix.sync.aligned.m8n8.x4.shared.b16 {%0,%1,%2,%3}, [%4];"
                 : "=r"(r[0]), "=r"(r[1]), "=r"(r[2]), "=r"(r[3]) : "r"(a));
}
__device__ __forceinline__ void mma16816(float* c, const unsigned* a, const unsigned* b) {
    asm volatile(
        "mma.sync.aligned.m16n8k16.row.col.f32.bf16.bf16.f32 "
        "{%0,%1,%2,%3}, {%4,%5,%6,%7}, {%8,%9}, {%0,%1,%2,%3};"
        : "+f"(c[0]), "+f"(c[1]), "+f"(c[2]), "+f"(c[3])
        : "r"(a[0]), "r"(a[1]), "r"(a[2]), "r"(a[3]), "r"(b[0]), "r"(b[1]));
}

__device__ __forceinline__ void split_bf16(float v, unsigned short& h, unsigned short& l) {
    __nv_bfloat16 hb = __float2bfloat16(v);
    float hf = __bfloat162float(hb);
    __nv_bfloat16 lb = __float2bfloat16(v - hf);
    h = *reinterpret_cast<unsigned short*>(&hb);
    l = *reinterpret_cast<unsigned short*>(&lb);
}

// ---------------------------------------------------------------------------
// Transpose + bf16 split: in [rows, C] fp32 -> out [C, R(=ld)] hi/lo
// ---------------------------------------------------------------------------
__global__ void __launch_bounds__(256)
conv_split_T(const float* __restrict__ in, unsigned short* __restrict__ oh,
             unsigned short* __restrict__ ol, int R, int C,
             size_t in_bs, size_t out_bs)
{
    __shared__ float t[32][33];
    const float* ib = in + (size_t)blockIdx.z * in_bs;
    int x = blockIdx.x * 32 + threadIdx.x;
    int y0 = blockIdx.y * 32 + threadIdx.y;
    #pragma unroll
    for (int i = 0; i < 32; i += 8)
        t[threadIdx.y + i][threadIdx.x] = ib[(size_t)(y0 + i) * C + x];
    __syncthreads();
    int orow0 = blockIdx.x * 32 + threadIdx.y;
    int ocol  = blockIdx.y * 32 + threadIdx.x;
    #pragma unroll
    for (int i = 0; i < 32; i += 8) {
        float v = t[threadIdx.x][threadIdx.y + i];
        unsigned short h, l;
        split_bf16(v, h, l);
        size_t o = (size_t)blockIdx.z * out_bs + (size_t)(orow0 + i) * R + ocol;
        oh[o] = h; ol[o] = l;
    }
}

__global__ void __launch_bounds__(256)
conv_split(const float* __restrict__ in, unsigned short* __restrict__ oh,
           unsigned short* __restrict__ ol, int n)
{
    int i = blockIdx.x * 256 + threadIdx.x;
    if (i < n) { unsigned short h, l; split_bf16(in[i], h, l); oh[i] = h; ol[i] = l; }
}

// ---------------------------------------------------------------------------
// bf16-split tensor-core GEMM (mma.sync):
//   C[m,n] = sum_k A[m,k]*B[n,k]   (both operands K-major, hi/lo pairs)
// 128x128 tile, BK=64, 8 warps (2m x 4n), double-buffered cp.async.
// mode 0: C[bz*strideC + m*ldc + n] = acc
// mode 1: C[(bz*DQ + m)*NQ + n] = acc + Feat[same] + Bias[m]
// ---------------------------------------------------------------------------
#define BM 128
#define BN 128
#define BK 64
#define STG 65536
#define AH_O 0
#define AL_O 16384
#define BH_O 32768
#define BL_O 49152
#define GSMEM (2*STG)

__global__ void __launch_bounds__(256)
gemm_mma(const unsigned short* __restrict__ Ah, const unsigned short* __restrict__ Al,
         const unsigned short* __restrict__ Bh, const unsigned short* __restrict__ Bl,
         float* __restrict__ C, const float* __restrict__ Feat, const float* __restrict__ Bias,
         int K, int ldc, size_t strideA, size_t strideB, size_t strideC, int mode)
{
    extern __shared__ char smdyn[];
    const unsigned sbase = smem_u32(smdyn);
    const int tid  = threadIdx.x;
    const int lane = tid & 31;
    const int wid  = tid >> 5;
    const int wm   = (wid >> 2) * 64;
    const int wn   = (wid & 3) * 32;
    const int m0 = blockIdx.y * BM;
    const int n0 = blockIdx.x * BN;
    const int bz = blockIdx.z;
    const unsigned short* Ahb = Ah + (size_t)bz * strideA;
    const unsigned short* Alb = Al + (size_t)bz * strideA;
    const unsigned short* Bhb = Bh + (size_t)bz * strideB;
    const unsigned short* Blb = Bl + (size_t)bz * strideB;

    float acc[4][4][4];
    #pragma unroll
    for (int i = 0; i < 4; i++)
        #pragma unroll
        for (int j = 0; j < 4; j++)
            #pragma unroll
            for (int p = 0; p < 4; p++) acc[i][j][p] = 0.f;

    const int KT = K / BK;

    // stage loader: 16 chunks of 16B per thread (4 per array), fully coalesced
    #define LOAD_STAGE(kt, st) do {                                              \
        unsigned so_ = sbase + (unsigned)(st) * STG;                             \
        int k0_ = (kt) * BK;                                                     \
        _Pragma("unroll")                                                        \
        for (int i_ = 0; i_ < 4; i_++) {                                         \
            int chunk_ = i_ * 256 + tid;                                         \
            int row_ = chunk_ >> 3, c_ = chunk_ & 7;                             \
            unsigned off_ = swz((unsigned)(row_ * 128 + c_ * 16));               \
            size_t ga_ = (size_t)(m0 + row_) * K + k0_ + c_ * 8;                 \
            size_t gb_ = (size_t)(n0 + row_) * K + k0_ + c_ * 8;                 \
            cpa16(so_ + AH_O + off_, Ahb + ga_);                                 \
            cpa16(so_ + AL_O + off_, Alb + ga_);                                 \
            cpa16(so_ + BH_O + off_, Bhb + gb_);                                 \
            cpa16(so_ + BL_O + off_, Blb + gb_);                                 \
        }                                                                        \
    } while (0)

    LOAD_STAGE(0, 0);
    CP_COMMIT();

    for (int kt = 0; kt < KT; kt++) {
        if (kt + 1 < KT) {
            LOAD_STAGE(kt + 1, (kt + 1) & 1);
            CP_COMMIT();
            CP_WAIT(1);
        } else {
            CP_WAIT(0);
        }
        __syncthreads();

        const unsigned sa = sbase + (unsigned)(kt & 1) * STG;
        #pragma unroll
        for (int ks = 0; ks < 4; ks++) {
            unsigned ahf[4][4], alf[4][4], bhf[4][2], blf[4][2];
            #pragma unroll
            for (int mi = 0; mi < 4; mi++) {
                int row = wm + mi * 16 + (lane & 15);
                int chunk = 2 * ks + (lane >> 4);
                unsigned off = swz((unsigned)(row * 128 + chunk * 16));
                ldsm4(ahf[mi], sa + AH_O + off);
                ldsm4(alf[mi], sa + AL_O + off);
            }
            #pragma unroll
            for (int j = 0; j < 2; j++) {
                int g = lane >> 3;
                int row = wn + (2 * j + (g >> 1)) * 8 + (lane & 7);
                int chunk = 2 * ks + (g & 1);
                unsigned off = swz((unsigned)(row * 128 + chunk * 16));
                unsigned t[4];
                ldsm4(t, sa + BH_O + off);
                bhf[2*j][0] = t[0]; bhf[2*j][1] = t[1];
                bhf[2*j+1][0] = t[2]; bhf[2*j+1][1] = t[3];
                ldsm4(t, sa + BL_O + off);
                blf[2*j][0] = t[0]; blf[2*j][1] = t[1];
                blf[2*j+1][0] = t[2]; blf[2*j+1][1] = t[3];
            }
            #pragma unroll
            for (int mi = 0; mi < 4; mi++)
                #pragma unroll
                for (int ni = 0; ni < 4; ni++) {
                    mma16816(acc[mi][ni], ahf[mi], bhf[ni]);
                    mma16816(acc[mi][ni], ahf[mi], blf[ni]);
                    mma16816(acc[mi][ni], alf[mi], bhf[ni]);
                }
        }
        __syncthreads();
    }

    // epilogue
    #pragma unroll
    for (int mi = 0; mi < 4; mi++) {
        #pragma unroll
        for (int ni = 0; ni < 4; ni++) {
            int m = m0 + wm + mi * 16 + (lane >> 2);
            int n = n0 + wn + ni * 8 + (lane & 3) * 2;
            const float* c = acc[mi][ni];
            if (mode == 0) {
                float2 v0 = make_float2(c[0], c[1]);
                float2 v1 = make_float2(c[2], c[3]);
                *(float2*)&C[(size_t)bz * strideC + (size_t)m * ldc + n]       = v0;
                *(float2*)&C[(size_t)bz * strideC + (size_t)(m + 8) * ldc + n] = v1;
            } else {
                size_t a0 = ((size_t)bz * DQ + m) * NQ + n;
                size_t a1 = ((size_t)bz * DQ + m + 8) * NQ + n;
                float b0 = Bias[m], b1 = Bias[m + 8];
                float2 f0 = *(const float2*)&Feat[a0];
                float2 f1 = *(const float2*)&Feat[a1];
                *(float2*)&C[a0] = make_float2(c[0] + f0.x + b0, c[1] + f0.y + b0);
                *(float2*)&C[a1] = make_float2(c[2] + f1.x + b1, c[3] + f1.y + b1);
            }
        }
    }
}

// ---------------------------------------------------------------------------
// Attention: one thread per query row (fp32), outputs bf16 hi/lo [B,Nq,Dq]
// ---------------------------------------------------------------------------
__global__ void __launch_bounds__(128)
attn_kernel()
{
    const int r  = threadIdx.x;
    const int h  = blockIdx.y;
    const int b  = blockIdx.z;
    const int n  = blockIdx.x * 128 + r;

    __shared__ float sk[64][64];
    __shared__ float sv[64][64];

    const float* kvb = g_kv + (size_t)b * NT * DKV2 + h * HD;
    for (int idx = r; idx < NT * HD; idx += 128) {
        int t = idx >> 6, j = idx & 63;
        sk[t][j] = kvb[(size_t)t * DKV2 + j];
        sv[t][j] = kvb[(size_t)t * DKV2 + DQ + j];
    }
    __syncthreads();

    for (int idx = r; idx < NT * 32; idx += 128) {
        int t = idx >> 5, i = idx & 31;
        float inv = exp2f((float)i * NEG_L2B_32);
        float sn, cs;
        sincosf((float)t * inv, &sn, &cs);
        float x1 = sk[t][i], x2 = sk[t][i + 32];
        sk[t][i]      = x1 * cs - x2 * sn;
        sk[t][i + 32] = x2 * cs + x1 * sn;
    }
    __syncthreads();

    float qr[64];
    const float* qrow = g_q + ((size_t)(b * NQ + n)) * DQ + h * HD;
    #pragma unroll
    for (int j4 = 0; j4 < 16; j4++) {
        float4 v = *(const float4*)&qrow[j4 * 4];
        qr[j4 * 4 + 0] = v.x; qr[j4 * 4 + 1] = v.y;
        qr[j4 * 4 + 2] = v.z; qr[j4 * 4 + 3] = v.w;
    }
    #pragma unroll
    for (int i = 0; i < 32; i++) {
        float inv = exp2f((float)i * NEG_L2B_32);
        float sn, cs;
        sincosf((float)n * inv, &sn, &cs);
        float x1 = qr[i], x2 = qr[i + 32];
        qr[i]      = x1 * cs - x2 * sn;
        qr[i + 32] = x2 * cs + x1 * sn;
    }

    float sreg[64];
    #pragma unroll
    for (int t = 0; t < 64; t++) {
        float ax = 0.f, ay = 0.f, az = 0.f, aw = 0.f;
        #pragma unroll
        for (int j4 = 0; j4 < 16; j4++) {
            float4 k4 = *(const float4*)&sk[t][j4 * 4];
            ax += qr[j4 * 4 + 0] * k4.x;
            ay += qr[j4 * 4 + 1] * k4.y;
            az += qr[j4 * 4 + 2] * k4.z;
            aw += qr[j4 * 4 + 3] * k4.w;
        }
        sreg[t] = 0.125f * ((ax + ay) + (az + aw));
    }

    float mx = sreg[0];
    #pragma unroll
    for (int t = 1; t < 64; t++) mx = fmaxf(mx, sreg[t]);
    float sum = 0.f;
    #pragma unroll
    for (int t = 0; t < 64; t++) { sreg[t] = expf(sreg[t] - mx); sum += sreg[t]; }
    float invs = 1.f / sum;

    float o[64];
    #pragma unroll
    for (int j = 0; j < 64; j++) o[j] = 0.f;
    #pragma unroll
    for (int t = 0; t < 64; t++) {
        float p = sreg[t];
        #pragma unroll
        for (int j4 = 0; j4 < 16; j4++) {
            float4 v4 = *(const float4*)&sv[t][j4 * 4];
            o[j4 * 4 + 0] += p * v4.x;
            o[j4 * 4 + 1] += p * v4.y;
            o[j4 * 4 + 2] += p * v4.z;
            o[j4 * 4 + 3] += p * v4.w;
        }
    }

    size_t obase = ((size_t)(b * NQ + n)) * DQ + h * HD;
    #pragma unroll
    for (int g = 0; g < 8; g++) {
        unsigned hw[4], lw[4];
        #pragma unroll
        for (int p = 0; p < 4; p++) {
            unsigned short h0, l0, h1, l1;
            split_bf16(o[g * 8 + p * 2 + 0] * invs, h0, l0);
            split_bf16(o[g * 8 + p * 2 + 1] * invs, h1, l1);
            hw[p] = (unsigned)h0 | ((unsigned)h1 << 16);
            lw[p] = (unsigned)l0 | ((unsigned)l1 << 16);
        }
        *(uint4*)(g_o_h + obase + g * 8) = make_uint4(hw[0], hw[1], hw[2], hw[3]);
        *(uint4*)(g_o_l + obase + g * 8) = make_uint4(lw[0], lw[1], lw[2], lw[3]);
    }
}

// ---------------------------------------------------------------------------
// Launch
// ---------------------------------------------------------------------------
extern "C" void kernel_launch(void* const* d_in, const int* in_sizes, int n_in,
                              void* d_out, int out_size)
{
    (void)in_sizes; (void)n_in; (void)out_size;
    const float* feat   = (const float*)d_in[0];
    const float* tokens = (const float*)d_in[1];
    const float* Wq     = (const float*)d_in[2];
    const float* Wkv    = (const float*)d_in[3];
    const float* Wout   = (const float*)d_in[4];
    const float* bout   = (const float*)d_in[5];
    float* outp = (float*)d_out;

    float *pq, *pkv;
    unsigned short *pqh, *pql, *poh, *pol, *pwqh, *pwql, *pwkh, *pwkl, *pwoh, *pwol, *pth, *ptl;
    cudaGetSymbolAddress((void**)&pq,   g_q);
    cudaGetSymbolAddress((void**)&pkv,  g_kv);
    cudaGetSymbolAddress((void**)&pqh,  g_qin_h);
    cudaGetSymbolAddress((void**)&pql,  g_qin_l);
    cudaGetSymbolAddress((void**)&poh,  g_o_h);
    cudaGetSymbolAddress((void**)&pol,  g_o_l);
    cudaGetSymbolAddress((void**)&pwqh, g_wqT_h);
    cudaGetSymbolAddress((void**)&pwql, g_wqT_l);
    cudaGetSymbolAddress((void**)&pwkh, g_wkvT_h);
    cudaGetSymbolAddress((void**)&pwkl, g_wkvT_l);
    cudaGetSymbolAddress((void**)&pwoh, g_woT_h);
    cudaGetSymbolAddress((void**)&pwol, g_woT_l);
    cudaGetSymbolAddress((void**)&pth,  g_tok_h);
    cudaGetSymbolAddress((void**)&ptl,  g_tok_l);

    cudaFuncSetAttribute(gemm_mma, cudaFuncAttributeMaxDynamicSharedMemorySize, GSMEM);

    // conversions / transposes into K-major bf16 hi/lo
    conv_split_T<<<dim3(NQ/32, DQ/32, BATCH), dim3(32, 8)>>>(
        feat, pqh, pql, DQ, NQ, (size_t)DQ*NQ, (size_t)NQ*DQ);
    conv_split_T<<<dim3(DQ/32, DQ/32, 1), dim3(32, 8)>>>(Wq,   pwqh, pwql, DQ,  DQ,   0, 0);
    conv_split_T<<<dim3(DKV2/32, DKV/32, 1), dim3(32, 8)>>>(Wkv, pwkh, pwkl, DKV, DKV2, 0, 0);
    conv_split_T<<<dim3(DQ/32, DQ/32, 1), dim3(32, 8)>>>(Wout, pwoh, pwol, DQ,  DQ,   0, 0);
    conv_split<<<(NKV*DKV + 255)/256, 256>>>(tokens, pth, ptl, NKV*DKV);

    // kv = tokens @ Wkv : C[tok, 1536], K=384
    gemm_mma<<<dim3(DKV2/BN, NKV/BM, 1), 256, GSMEM>>>(
        pth, ptl, pwkh, pwkl, pkv, nullptr, nullptr,
        DKV, DKV2, 0, 0, 0, 0);

    // q = q_in @ Wq per batch : C[q, Dq], K=768
    gemm_mma<<<dim3(DQ/BN, NQ/BM, BATCH), 256, GSMEM>>>(
        pqh, pql, pwqh, pwql, pq, nullptr, nullptr,
        DQ, DQ, (size_t)NQ*DQ, 0, (size_t)NQ*DQ, 0);

    // attention (RoPE + softmax + PV), outputs bf16 hi/lo [B,Nq,Dq]
    attn_kernel<<<dim3(NQ/128, NH, BATCH), 128>>>();

    // out[d, q] = feat + (o @ Wout)^T + bout : m=d (A=WoutT), n=q (B=o), K=768
    gemm_mma<<<dim3(NQ/BN, DQ/BM, BATCH), 256, GSMEM>>>(
        pwoh, pwol, poh, pol, outp, feat, bout,
        DQ, 0, 0, (size_t)NQ*DQ, 0, 1);
}

// round 4
// speedup vs baseline: 3.7392x; 1.4311x over previous
#include <cuda_runtime.h>
#include <cuda_bf16.h>
#include <math.h>

// Problem constants
#define BATCH 16
#define DQ    768
#define NQ    1024
#define NT    64
#define DKV   384
#define NH    12
#define HD    64
#define NKV   (BATCH*NT)
#define DKV2  (2*DQ)

#define NEG_L2B_32 (-0.41524101186091903f)   // -log2(10000)/32

typedef unsigned short u16;
typedef unsigned int   u32;

// ---------------------------------------------------------------------------
// Scratch (device globals)
// ---------------------------------------------------------------------------
__device__ __align__(16) u16 g_qin_h[(size_t)BATCH*NQ*DQ];  // feat^T split
__device__ __align__(16) u16 g_qin_l[(size_t)BATCH*NQ*DQ];
__device__ __align__(16) u16 g_qr_h [(size_t)BATCH*NQ*DQ];  // rope'd q [B,Nq,Dq]
__device__ __align__(16) u16 g_qr_l [(size_t)BATCH*NQ*DQ];
__device__ __align__(16) u16 g_k_h  [(size_t)BATCH*NH*NT*HD];   // rope'd K [b,h,t,hd]
__device__ __align__(16) u16 g_k_l  [(size_t)BATCH*NH*NT*HD];
__device__ __align__(16) u16 g_vT_h [(size_t)BATCH*NH*HD*NT];   // V^T [b,h,hd,t]
__device__ __align__(16) u16 g_vT_l [(size_t)BATCH*NH*HD*NT];
__device__ __align__(16) u16 g_o_h  [(size_t)BATCH*NQ*DQ];  // attn out [B,Nq,Dq]
__device__ __align__(16) u16 g_o_l  [(size_t)BATCH*NQ*DQ];
__device__ __align__(16) u16 g_wqT_h[DQ*DQ],     g_wqT_l[DQ*DQ];
__device__ __align__(16) u16 g_wkvT_h[DKV2*DKV], g_wkvT_l[DKV2*DKV];
__device__ __align__(16) u16 g_woT_h[DQ*DQ],     g_woT_l[DQ*DQ];
__device__ __align__(16) u16 g_tok_h[NKV*DKV],   g_tok_l[NKV*DKV];
__device__ __align__(16) float2 g_cs[NQ*32];     // (cos, sin) table

// ---------------------------------------------------------------------------
// Helpers (base-ISA only)
// ---------------------------------------------------------------------------
__device__ __forceinline__ u32 smem_u32(const void* p) {
    u32 a;
    asm("{ .reg .u64 t; cvta.to.shared.u64 t, %1; cvt.u32.u64 %0, t; }" : "=r"(a) : "l"(p));
    return a;
}
__device__ __forceinline__ u32 swz(u32 o) { return o ^ ((o >> 3) & 0x70); }

__device__ __forceinline__ void cpa16(u32 s, const void* g) {
    asm volatile("cp.async.cg.shared.global [%0], [%1], 16;" :: "r"(s), "l"(g) : "memory");
}
#define CP_COMMIT() asm volatile("cp.async.commit_group;" ::: "memory")
#define CP_WAIT(n)  asm volatile("cp.async.wait_group %0;" :: "n"(n) : "memory")

__device__ __forceinline__ void ldsm4(u32* r, u32 a) {
    asm volatile("ldmatrix.sync.aligned.m8n8.x4.shared.b16 {%0,%1,%2,%3}, [%4];"
                 : "=r"(r[0]), "=r"(r[1]), "=r"(r[2]), "=r"(r[3]) : "r"(a));
}
__device__ __forceinline__ void mma16816(float* c, const u32* a, const u32* b) {
    asm volatile(
        "mma.sync.aligned.m16n8k16.row.col.f32.bf16.bf16.f32 "
        "{%0,%1,%2,%3}, {%4,%5,%6,%7}, {%8,%9}, {%0,%1,%2,%3};"
        : "+f"(c[0]), "+f"(c[1]), "+f"(c[2]), "+f"(c[3])
        : "r"(a[0]), "r"(a[1]), "r"(a[2]), "r"(a[3]), "r"(b[0]), "r"(b[1]));
}

__device__ __forceinline__ void split_bf16(float v, u16& h, u16& l) {
    __nv_bfloat16 hb = __float2bfloat16(v);
    float hf = __bfloat162float(hb);
    __nv_bfloat16 lb = __float2bfloat16(v - hf);
    h = *reinterpret_cast<u16*>(&hb);
    l = *reinterpret_cast<u16*>(&lb);
}
// pack 2 floats -> bf16x2 hi word + lo-residual word
__device__ __forceinline__ void split_pack(float a, float b, u32& ph, u32& pl) {
    u16 ha, la, hb, lb;
    split_bf16(a, ha, la);
    split_bf16(b, hb, lb);
    ph = (u32)ha | ((u32)hb << 16);
    pl = (u32)la | ((u32)lb << 16);
}

// ---------------------------------------------------------------------------
// RoPE cos/sin table: g_cs[pos*32 + i] = (cos, sin)(pos * 10000^{-i/32})
// ---------------------------------------------------------------------------
__global__ void __launch_bounds__(256)
rope_table()
{
    int idx = blockIdx.x * 256 + threadIdx.x;
    if (idx < NQ * 32) {
        int pos = idx >> 5, i = idx & 31;
        float inv = exp2f((float)i * NEG_L2B_32);
        float sn, cs;
        sincosf((float)pos * inv, &sn, &cs);
        g_cs[idx] = make_float2(cs, sn);
    }
}

// ---------------------------------------------------------------------------
// Transpose + bf16 split: in [rows, C] fp32 -> out [C][rows] hi/lo (ld = R)
// ---------------------------------------------------------------------------
__global__ void __launch_bounds__(256)
conv_split_T(const float* __restrict__ in, u16* __restrict__ oh,
             u16* __restrict__ ol, int R, int C, size_t in_bs, size_t out_bs)
{
    __shared__ float t[32][33];
    const float* ib = in + (size_t)blockIdx.z * in_bs;
    int x = blockIdx.x * 32 + threadIdx.x;
    int y0 = blockIdx.y * 32 + threadIdx.y;
    #pragma unroll
    for (int i = 0; i < 32; i += 8)
        t[threadIdx.y + i][threadIdx.x] = ib[(size_t)(y0 + i) * C + x];
    __syncthreads();
    int orow0 = blockIdx.x * 32 + threadIdx.y;
    int ocol  = blockIdx.y * 32 + threadIdx.x;
    #pragma unroll
    for (int i = 0; i < 32; i += 8) {
        float v = t[threadIdx.x][threadIdx.y + i];
        u16 h, l;
        split_bf16(v, h, l);
        size_t o = (size_t)blockIdx.z * out_bs + (size_t)(orow0 + i) * R + ocol;
        oh[o] = h; ol[o] = l;
    }
}

__global__ void __launch_bounds__(256)
conv_split(const float* __restrict__ in, u16* __restrict__ oh,
           u16* __restrict__ ol, int n)
{
    int i = blockIdx.x * 256 + threadIdx.x;
    if (i < n) { u16 h, l; split_bf16(in[i], h, l); oh[i] = h; ol[i] = l; }
}

// ---------------------------------------------------------------------------
// bf16-split tensor GEMM: C[m,n] = sum_k A[m,k]*B[n,k], K-major hi/lo operands
// 128x128 tile, BK=64, 8 warps (4m x 2n => warp 32m x 64n), 3-stage cp.async.
// MODE 1: C[(bz*DQ+m)*NQ+n] = acc + Feat[..] + Bias[m]          (out proj)
// MODE 2: RoPE(m, n%64) -> g_qr hi/lo at [(bz*NQ+m)*DQ+n]       (q proj)
// MODE 3: n<768: RoPE K -> g_k[b,h,t,hd]; n>=768: V^T -> g_vT   (kv proj)
// ---------------------------------------------------------------------------
#define BK 64
#define STG 65536
#define AH_O 0
#define AL_O 16384
#define BH_O 32768
#define BL_O 49152
#define GSMEM (3*STG)

template<int MODE>
__global__ void __launch_bounds__(256)
gemm_mma(const u16* __restrict__ Ah, const u16* __restrict__ Al,
         const u16* __restrict__ Bh, const u16* __restrict__ Bl,
         float* __restrict__ C, const float* __restrict__ Feat,
         const float* __restrict__ Bias, int K, size_t sA, size_t sB)
{
    extern __shared__ char smdyn[];
    const u32 sbase = smem_u32(smdyn);
    const int tid  = threadIdx.x;
    const int lane = tid & 31;
    const int wid  = tid >> 5;
    const int wm   = (wid & 3) * 32;
    const int wn   = (wid >> 2) * 64;
    const int m0 = blockIdx.y * 128;
    const int n0 = blockIdx.x * 128;
    const int bz = blockIdx.z;
    const u16* Ahb = Ah + (size_t)bz * sA;
    const u16* Alb = Al + (size_t)bz * sA;
    const u16* Bhb = Bh + (size_t)bz * sB;
    const u16* Blb = Bl + (size_t)bz * sB;

    float acc[2][8][4];
    #pragma unroll
    for (int i = 0; i < 2; i++)
        #pragma unroll
        for (int j = 0; j < 8; j++)
            #pragma unroll
            for (int p = 0; p < 4; p++) acc[i][j][p] = 0.f;

    const int KT = K / BK;

    #define LOAD_STAGE(kt, slot) do {                                           \
        u32 so_ = sbase + (u32)(slot) * STG;                                    \
        int k0_ = (kt) * BK;                                                    \
        _Pragma("unroll")                                                       \
        for (int i_ = 0; i_ < 4; i_++) {                                        \
            int chunk_ = i_ * 256 + tid;                                        \
            int row_ = chunk_ >> 3, c_ = chunk_ & 7;                            \
            u32 off_ = swz((u32)(row_ * 128 + c_ * 16));                        \
            size_t ga_ = (size_t)(m0 + row_) * K + k0_ + c_ * 8;                \
            size_t gb_ = (size_t)(n0 + row_) * K + k0_ + c_ * 8;                \
            cpa16(so_ + AH_O + off_, Ahb + ga_);                                \
            cpa16(so_ + AL_O + off_, Alb + ga_);                                \
            cpa16(so_ + BH_O + off_, Bhb + gb_);                                \
            cpa16(so_ + BL_O + off_, Blb + gb_);                                \
        }                                                                       \
    } while (0)

    LOAD_STAGE(0, 0);
    CP_COMMIT();
    if (KT > 1) { LOAD_STAGE(1, 1); CP_COMMIT(); }

    int slot = 0;
    for (int kt = 0; kt < KT; kt++) {
        if (kt + 1 < KT) CP_WAIT(1); else CP_WAIT(0);
        __syncthreads();
        if (kt + 2 < KT) {
            int ns = slot + 2; if (ns >= 3) ns -= 3;
            LOAD_STAGE(kt + 2, ns);
            CP_COMMIT();
        }
        const u32 sa = sbase + (u32)slot * STG;
        #pragma unroll
        for (int ks = 0; ks < 4; ks++) {
            u32 ahf[2][4], alf[2][4], bhf[8][2], blf[8][2];
            #pragma unroll
            for (int mi = 0; mi < 2; mi++) {
                int row = wm + mi * 16 + (lane & 15);
                int chunk = 2 * ks + (lane >> 4);
                u32 off = swz((u32)(row * 128 + chunk * 16));
                ldsm4(ahf[mi], sa + AH_O + off);
                ldsm4(alf[mi], sa + AL_O + off);
            }
            #pragma unroll
            for (int jj = 0; jj < 4; jj++) {
                int g = lane >> 3;
                int row = wn + (2 * jj + (g >> 1)) * 8 + (lane & 7);
                int chunk = 2 * ks + (g & 1);
                u32 off = swz((u32)(row * 128 + chunk * 16));
                u32 t[4];
                ldsm4(t, sa + BH_O + off);
                bhf[2*jj][0] = t[0]; bhf[2*jj][1] = t[1];
                bhf[2*jj+1][0] = t[2]; bhf[2*jj+1][1] = t[3];
                ldsm4(t, sa + BL_O + off);
                blf[2*jj][0] = t[0]; blf[2*jj][1] = t[1];
                blf[2*jj+1][0] = t[2]; blf[2*jj+1][1] = t[3];
            }
            #pragma unroll
            for (int mi = 0; mi < 2; mi++)
                #pragma unroll
                for (int ni = 0; ni < 8; ni++) {
                    mma16816(acc[mi][ni], ahf[mi], bhf[ni]);
                    mma16816(acc[mi][ni], ahf[mi], blf[ni]);
                    mma16816(acc[mi][ni], alf[mi], bhf[ni]);
                }
        }
        __syncthreads();
        slot++; if (slot >= 3) slot = 0;
    }

    // ---- epilogues ----
    if (MODE == 1) {
        #pragma unroll
        for (int mi = 0; mi < 2; mi++)
            #pragma unroll
            for (int ni = 0; ni < 8; ni++) {
                int m = m0 + wm + mi * 16 + (lane >> 2);
                int n = n0 + wn + ni * 8 + (lane & 3) * 2;
                const float* c = acc[mi][ni];
                size_t a0 = ((size_t)bz * DQ + m) * NQ + n;
                size_t a1 = ((size_t)bz * DQ + m + 8) * NQ + n;
                float b0 = Bias[m], b1 = Bias[m + 8];
                float2 f0 = *(const float2*)&Feat[a0];
                float2 f1 = *(const float2*)&Feat[a1];
                *(float2*)&C[a0] = make_float2(c[0] + f0.x + b0, c[1] + f0.y + b0);
                *(float2*)&C[a1] = make_float2(c[2] + f1.x + b1, c[3] + f1.y + b1);
            }
    } else if (MODE == 2) {
        #pragma unroll
        for (int mi = 0; mi < 2; mi++)
            #pragma unroll
            for (int ni = 0; ni < 4; ni++)
                #pragma unroll
                for (int half = 0; half < 2; half++) {
                    int m = m0 + wm + mi * 16 + (lane >> 2) + half * 8;
                    int i0 = ni * 8 + (lane & 3) * 2;       // i_loc in [0,32)
                    float2 cs0 = g_cs[m * 32 + i0];
                    float2 cs1 = g_cs[m * 32 + i0 + 1];
                    float x1a = acc[mi][ni][half*2],   x2a = acc[mi][ni+4][half*2];
                    float x1b = acc[mi][ni][half*2+1], x2b = acc[mi][ni+4][half*2+1];
                    float y1a = x1a * cs0.x - x2a * cs0.y;
                    float y2a = x2a * cs0.x + x1a * cs0.y;
                    float y1b = x1b * cs1.x - x2b * cs1.y;
                    float y2b = x2b * cs1.x + x1b * cs1.y;
                    int n = n0 + wn + i0;
                    size_t base = ((size_t)bz * NQ + m) * DQ;
                    u32 ph, pl;
                    split_pack(y1a, y1b, ph, pl);
                    *(u32*)&g_qr_h[base + n] = ph;
                    *(u32*)&g_qr_l[base + n] = pl;
                    split_pack(y2a, y2b, ph, pl);
                    *(u32*)&g_qr_h[base + n + 32] = ph;
                    *(u32*)&g_qr_l[base + n + 32] = pl;
                }
    } else { // MODE 3 : kv
        if (n0 + wn < DQ) {
            // K half with RoPE
            #pragma unroll
            for (int mi = 0; mi < 2; mi++)
                #pragma unroll
                for (int ni = 0; ni < 4; ni++)
                    #pragma unroll
                    for (int half = 0; half < 2; half++) {
                        int m = m0 + wm + mi * 16 + (lane >> 2) + half * 8;
                        int bb = m >> 6, t = m & 63;
                        int n = n0 + wn + ni * 8 + (lane & 3) * 2;
                        int h = n >> 6;
                        int i0 = n & 63;                    // < 32
                        float2 cs0 = g_cs[t * 32 + i0];
                        float2 cs1 = g_cs[t * 32 + i0 + 1];
                        float x1a = acc[mi][ni][half*2],   x2a = acc[mi][ni+4][half*2];
                        float x1b = acc[mi][ni][half*2+1], x2b = acc[mi][ni+4][half*2+1];
                        float y1a = x1a * cs0.x - x2a * cs0.y;
                        float y2a = x2a * cs0.x + x1a * cs0.y;
                        float y1b = x1b * cs1.x - x2b * cs1.y;
                        float y2b = x2b * cs1.x + x1b * cs1.y;
                        size_t base = (((size_t)bb * NH + h) * NT + t) * HD;
                        u32 ph, pl;
                        split_pack(y1a, y1b, ph, pl);
                        *(u32*)&g_k_h[base + i0] = ph;
                        *(u32*)&g_k_l[base + i0] = pl;
                        split_pack(y2a, y2b, ph, pl);
                        *(u32*)&g_k_h[base + i0 + 32] = ph;
                        *(u32*)&g_k_l[base + i0 + 32] = pl;
                    }
        } else {
            // V half, store transposed [b,h,hd,t]
            #pragma unroll
            for (int mi = 0; mi < 2; mi++)
                #pragma unroll
                for (int ni = 0; ni < 8; ni++)
                    #pragma unroll
                    for (int p = 0; p < 4; p++) {
                        int m = m0 + wm + mi * 16 + (lane >> 2) + (p >> 1) * 8;
                        int bb = m >> 6, t = m & 63;
                        int n = n0 + wn + ni * 8 + (lane & 3) * 2 + (p & 1);
                        int h = (n - DQ) >> 6;
                        int hd = n & 63;
                        u16 hh, ll;
                        split_bf16(acc[mi][ni][p], hh, ll);
                        size_t o = (((size_t)bb * NH + h) * HD + hd) * NT + t;
                        g_vT_h[o] = hh; g_vT_l[o] = ll;
                    }
        }
    }
    #undef LOAD_STAGE
}

// ---------------------------------------------------------------------------
// Tensor-core attention: grid (NQ/128, NH, BATCH), 128 threads (4 warps).
// Warp = 32 q-rows x 64 keys. S and O via 3-pass bf16-split mma;
// softmax + P split fully in registers.
// ---------------------------------------------------------------------------
#define AQH 0
#define AQL 16384
#define AKH 32768
#define AKL 40960
#define AVH 49152
#define AVL 57344
#define ASMEM 65536

__global__ void __launch_bounds__(128)
attn_tc()
{
    extern __shared__ char smdyn[];
    const u32 sbase = smem_u32(smdyn);
    const int tid  = threadIdx.x;
    const int lane = tid & 31;
    const int wid  = tid >> 5;
    const int q0 = blockIdx.x * 128;
    const int h  = blockIdx.y;
    const int b  = blockIdx.z;

    // loads: q tile 128 rows x 64 bf16 (hi+lo), k & vT 64 rows x 64 bf16
    {
        const u16* qh = g_qr_h + ((size_t)(b * NQ + q0)) * DQ + h * HD;
        const u16* ql = g_qr_l + ((size_t)(b * NQ + q0)) * DQ + h * HD;
        #pragma unroll
        for (int i = 0; i < 8; i++) {
            int c = i * 128 + tid;
            int row = c >> 3, cc = c & 7;
            u32 off = swz((u32)(row * 128 + cc * 16));
            cpa16(sbase + AQH + off, qh + (size_t)row * DQ + cc * 8);
            cpa16(sbase + AQL + off, ql + (size_t)row * DQ + cc * 8);
        }
        size_t kvb = ((size_t)b * NH + h) * (NT * HD);
        #pragma unroll
        for (int i = 0; i < 4; i++) {
            int c = i * 128 + tid;
            int row = c >> 3, cc = c & 7;
            u32 off = swz((u32)(row * 128 + cc * 16));
            cpa16(sbase + AKH + off, g_k_h  + kvb + row * 64 + cc * 8);
            cpa16(sbase + AKL + off, g_k_l  + kvb + row * 64 + cc * 8);
            cpa16(sbase + AVH + off, g_vT_h + kvb + row * 64 + cc * 8);
            cpa16(sbase + AVL + off, g_vT_l + kvb + row * 64 + cc * 8);
        }
        CP_COMMIT();
        CP_WAIT(0);
        __syncthreads();
    }

    // S = Q K^T (3-pass split)
    float s[2][8][4];
    #pragma unroll
    for (int i = 0; i < 2; i++)
        #pragma unroll
        for (int j = 0; j < 8; j++)
            #pragma unroll
            for (int p = 0; p < 4; p++) s[i][j][p] = 0.f;

    #pragma unroll
    for (int ks = 0; ks < 4; ks++) {
        u32 aqh[2][4], aql[2][4], bkh[8][2], bkl[8][2];
        #pragma unroll
        for (int mi = 0; mi < 2; mi++) {
            int row = wid * 32 + mi * 16 + (lane & 15);
            int chunk = 2 * ks + (lane >> 4);
            u32 off = swz((u32)(row * 128 + chunk * 16));
            ldsm4(aqh[mi], sbase + AQH + off);
            ldsm4(aql[mi], sbase + AQL + off);
        }
        #pragma unroll
        for (int jj = 0; jj < 4; jj++) {
            int g = lane >> 3;
            int row = (2 * jj + (g >> 1)) * 8 + (lane & 7);
            int chunk = 2 * ks + (g & 1);
            u32 off = swz((u32)(row * 128 + chunk * 16));
            u32 t[4];
            ldsm4(t, sbase + AKH + off);
            bkh[2*jj][0] = t[0]; bkh[2*jj][1] = t[1];
            bkh[2*jj+1][0] = t[2]; bkh[2*jj+1][1] = t[3];
            ldsm4(t, sbase + AKL + off);
            bkl[2*jj][0] = t[0]; bkl[2*jj][1] = t[1];
            bkl[2*jj+1][0] = t[2]; bkl[2*jj+1][1] = t[3];
        }
        #pragma unroll
        for (int mi = 0; mi < 2; mi++)
            #pragma unroll
            for (int ni = 0; ni < 8; ni++) {
                mma16816(s[mi][ni], aqh[mi], bkh[ni]);
                mma16816(s[mi][ni], aqh[mi], bkl[ni]);
                mma16816(s[mi][ni], aql[mi], bkh[ni]);
            }
    }

    // softmax (scale 1/8), rows r=(lane>>2) [p 0,1] and r+8 [p 2,3]
    #pragma unroll
    for (int mi = 0; mi < 2; mi++) {
        float mx0 = -1e30f, mx1 = -1e30f;
        #pragma unroll
        for (int ni = 0; ni < 8; ni++) {
            #pragma unroll
            for (int p = 0; p < 4; p++) s[mi][ni][p] *= 0.125f;
            mx0 = fmaxf(mx0, fmaxf(s[mi][ni][0], s[mi][ni][1]));
            mx1 = fmaxf(mx1, fmaxf(s[mi][ni][2], s[mi][ni][3]));
        }
        mx0 = fmaxf(mx0, __shfl_xor_sync(0xffffffffu, mx0, 1));
        mx0 = fmaxf(mx0, __shfl_xor_sync(0xffffffffu, mx0, 2));
        mx1 = fmaxf(mx1, __shfl_xor_sync(0xffffffffu, mx1, 1));
        mx1 = fmaxf(mx1, __shfl_xor_sync(0xffffffffu, mx1, 2));
        float sm0 = 0.f, sm1 = 0.f;
        #pragma unroll
        for (int ni = 0; ni < 8; ni++) {
            s[mi][ni][0] = __expf(s[mi][ni][0] - mx0);
            s[mi][ni][1] = __expf(s[mi][ni][1] - mx0);
            s[mi][ni][2] = __expf(s[mi][ni][2] - mx1);
            s[mi][ni][3] = __expf(s[mi][ni][3] - mx1);
            sm0 += s[mi][ni][0] + s[mi][ni][1];
            sm1 += s[mi][ni][2] + s[mi][ni][3];
        }
        sm0 += __shfl_xor_sync(0xffffffffu, sm0, 1);
        sm0 += __shfl_xor_sync(0xffffffffu, sm0, 2);
        sm1 += __shfl_xor_sync(0xffffffffu, sm1, 1);
        sm1 += __shfl_xor_sync(0xffffffffu, sm1, 2);
        float i0 = 1.f / sm0, i1 = 1.f / sm1;
        #pragma unroll
        for (int ni = 0; ni < 8; ni++) {
            s[mi][ni][0] *= i0; s[mi][ni][1] *= i0;
            s[mi][ni][2] *= i1; s[mi][ni][3] *= i1;
        }
    }

    // O = P V (P built from registers; 3-pass split)
    float o[2][8][4];
    #pragma unroll
    for (int i = 0; i < 2; i++)
        #pragma unroll
        for (int j = 0; j < 8; j++)
            #pragma unroll
            for (int p = 0; p < 4; p++) o[i][j][p] = 0.f;

    #pragma unroll
    for (int kc = 0; kc < 4; kc++) {
        u32 pah[2][4], pal[2][4], bvh[8][2], bvl[8][2];
        #pragma unroll
        for (int mi = 0; mi < 2; mi++) {
            split_pack(s[mi][2*kc][0],   s[mi][2*kc][1],   pah[mi][0], pal[mi][0]);
            split_pack(s[mi][2*kc][2],   s[mi][2*kc][3],   pah[mi][1], pal[mi][1]);
            split_pack(s[mi][2*kc+1][0], s[mi][2*kc+1][1], pah[mi][2], pal[mi][2]);
            split_pack(s[mi][2*kc+1][2], s[mi][2*kc+1][3], pah[mi][3], pal[mi][3]);
        }
        #pragma unroll
        for (int jj = 0; jj < 4; jj++) {
            int g = lane >> 3;
            int row = (2 * jj + (g >> 1)) * 8 + (lane & 7);
            int chunk = 2 * kc + (g & 1);
            u32 off = swz((u32)(row * 128 + chunk * 16));
            u32 t[4];
            ldsm4(t, sbase + AVH + off);
            bvh[2*jj][0] = t[0]; bvh[2*jj][1] = t[1];
            bvh[2*jj+1][0] = t[2]; bvh[2*jj+1][1] = t[3];
            ldsm4(t, sbase + AVL + off);
            bvl[2*jj][0] = t[0]; bvl[2*jj][1] = t[1];
            bvl[2*jj+1][0] = t[2]; bvl[2*jj+1][1] = t[3];
        }
        #pragma unroll
        for (int mi = 0; mi < 2; mi++)
            #pragma unroll
            for (int ni = 0; ni < 8; ni++) {
                mma16816(o[mi][ni], pah[mi], bvh[ni]);
                mma16816(o[mi][ni], pah[mi], bvl[ni]);
                mma16816(o[mi][ni], pal[mi], bvh[ni]);
            }
    }

    // store O as bf16 hi/lo at [B,Nq,Dq]
    #pragma unroll
    for (int mi = 0; mi < 2; mi++)
        #pragma unroll
        for (int ni = 0; ni < 8; ni++) {
            int q = q0 + wid * 32 + mi * 16 + (lane >> 2);
            int col = h * HD + ni * 8 + (lane & 3) * 2;
            u32 ph, pl;
            split_pack(o[mi][ni][0], o[mi][ni][1], ph, pl);
            size_t a0 = ((size_t)(b * NQ + q)) * DQ + col;
            *(u32*)&g_o_h[a0] = ph;
            *(u32*)&g_o_l[a0] = pl;
            split_pack(o[mi][ni][2], o[mi][ni][3], ph, pl);
            size_t a1 = ((size_t)(b * NQ + q + 8)) * DQ + col;
            *(u32*)&g_o_h[a1] = ph;
            *(u32*)&g_o_l[a1] = pl;
        }
}

// ---------------------------------------------------------------------------
// Launch
// ---------------------------------------------------------------------------
extern "C" void kernel_launch(void* const* d_in, const int* in_sizes, int n_in,
                              void* d_out, int out_size)
{
    (void)in_sizes; (void)n_in; (void)out_size;
    const float* feat   = (const float*)d_in[0];
    const float* tokens = (const float*)d_in[1];
    const float* Wq     = (const float*)d_in[2];
    const float* Wkv    = (const float*)d_in[3];
    const float* Wout   = (const float*)d_in[4];
    const float* bout   = (const float*)d_in[5];
    float* outp = (float*)d_out;

    u16 *pqih, *pqil, *pwqh, *pwql, *pwkh, *pwkl, *pwoh, *pwol, *pth, *ptl, *poh, *pol;
    cudaGetSymbolAddress((void**)&pqih, g_qin_h);
    cudaGetSymbolAddress((void**)&pqil, g_qin_l);
    cudaGetSymbolAddress((void**)&pwqh, g_wqT_h);
    cudaGetSymbolAddress((void**)&pwql, g_wqT_l);
    cudaGetSymbolAddress((void**)&pwkh, g_wkvT_h);
    cudaGetSymbolAddress((void**)&pwkl, g_wkvT_l);
    cudaGetSymbolAddress((void**)&pwoh, g_woT_h);
    cudaGetSymbolAddress((void**)&pwol, g_woT_l);
    cudaGetSymbolAddress((void**)&pth,  g_tok_h);
    cudaGetSymbolAddress((void**)&ptl,  g_tok_l);
    cudaGetSymbolAddress((void**)&poh,  g_o_h);
    cudaGetSymbolAddress((void**)&pol,  g_o_l);

    cudaFuncSetAttribute(gemm_mma<1>, cudaFuncAttributeMaxDynamicSharedMemorySize, GSMEM);
    cudaFuncSetAttribute(gemm_mma<2>, cudaFuncAttributeMaxDynamicSharedMemorySize, GSMEM);
    cudaFuncSetAttribute(gemm_mma<3>, cudaFuncAttributeMaxDynamicSharedMemorySize, GSMEM);
    cudaFuncSetAttribute(attn_tc,     cudaFuncAttributeMaxDynamicSharedMemorySize, ASMEM);

    rope_table<<<(NQ*32 + 255)/256, 256>>>();

    conv_split_T<<<dim3(NQ/32, DQ/32, BATCH), dim3(32, 8)>>>(
        feat, pqih, pqil, DQ, NQ, (size_t)DQ*NQ, (size_t)NQ*DQ);
    conv_split_T<<<dim3(DQ/32, DQ/32, 1), dim3(32, 8)>>>(Wq,   pwqh, pwql, DQ,  DQ,   0, 0);
    conv_split_T<<<dim3(DKV2/32, DKV/32, 1), dim3(32, 8)>>>(Wkv, pwkh, pwkl, DKV, DKV2, 0, 0);
    conv_split_T<<<dim3(DQ/32, DQ/32, 1), dim3(32, 8)>>>(Wout, pwoh, pwol, DQ,  DQ,   0, 0);
    conv_split<<<(NKV*DKV + 255)/256, 256>>>(tokens, pth, ptl, NKV*DKV);

    // kv = tokens @ Wkv -> RoPE'd K + transposed V (bf16 hi/lo)
    gemm_mma<3><<<dim3(DKV2/128, NKV/128, 1), 256, GSMEM>>>(
        pth, ptl, pwkh, pwkl, nullptr, nullptr, nullptr, DKV, 0, 0);

    // q = q_in @ Wq -> RoPE'd q (bf16 hi/lo)
    gemm_mma<2><<<dim3(DQ/128, NQ/128, BATCH), 256, GSMEM>>>(
        pqih, pqil, pwqh, pwql, nullptr, nullptr, nullptr, DQ, (size_t)NQ*DQ, 0);

    // attention (tensor cores)
    attn_tc<<<dim3(NQ/128, NH, BATCH), 128, ASMEM>>>();

    // out[d,q] = feat + (o @ Wout)^T + bout
    gemm_mma<1><<<dim3(NQ/128, DQ/128, BATCH), 256, GSMEM>>>(
        pwoh, pwol, poh, pol, outp, feat, bout, DQ, 0, (size_t)NQ*DQ);
}

// round 5
// speedup vs baseline: 4.8006x; 1.2839x over previous
#include <cuda_runtime.h>
#include <cuda_fp16.h>
#include <math.h>

// Problem constants
#define BATCH 16
#define DQ    768
#define NQ    1024
#define NT    64
#define DKV   384
#define NH    12
#define HD    64
#define NKV   (BATCH*NT)
#define DKV2  (2*DQ)

#define NEG_L2B_32 (-0.41524101186091903f)   // -log2(10000)/32

typedef unsigned short u16;
typedef unsigned int   u32;

// ---------------------------------------------------------------------------
// Scratch (device globals)
// ---------------------------------------------------------------------------
__device__ __align__(16) u16 g_qin_h[(size_t)BATCH*NQ*DQ];  // feat^T hi/lo fp16
__device__ __align__(16) u16 g_qin_l[(size_t)BATCH*NQ*DQ];
__device__ __align__(16) u16 g_qr_h [(size_t)BATCH*NQ*DQ];  // rope'd q hi/lo
__device__ __align__(16) u16 g_qr_l [(size_t)BATCH*NQ*DQ];
__device__ __align__(16) u16 g_k_h  [(size_t)BATCH*NH*NT*HD];  // rope'd K hi [b,h,t,hd]
__device__ __align__(16) u16 g_vT_h [(size_t)BATCH*NH*HD*NT];  // V^T hi [b,h,hd,t]
__device__ __align__(16) u16 g_o_h  [(size_t)BATCH*NQ*DQ];  // attn out hi [B,Nq,Dq]
__device__ __align__(16) u16 g_wq_h [DQ*DQ];                // WqT hi
__device__ __align__(16) u16 g_wkv_h[DKV2*DKV];             // WkvT hi
__device__ __align__(16) u16 g_wo_h [DQ*DQ], g_wo_l[DQ*DQ]; // WoutT hi/lo (A operand)
__device__ __align__(16) u16 g_tok_h[NKV*DKV], g_tok_l[NKV*DKV];
__device__ __align__(16) float2 g_cs[NQ*32];                // (cos, sin)

// ---------------------------------------------------------------------------
// Helpers (base-ISA only)
// ---------------------------------------------------------------------------
__device__ __forceinline__ u32 smem_u32(const void* p) {
    u32 a;
    asm("{ .reg .u64 t; cvta.to.shared.u64 t, %1; cvt.u32.u64 %0, t; }" : "=r"(a) : "l"(p));
    return a;
}
__device__ __forceinline__ u32 swz(u32 o) { return o ^ ((o >> 3) & 0x70); }

__device__ __forceinline__ void cpa16(u32 s, const void* g) {
    asm volatile("cp.async.cg.shared.global [%0], [%1], 16;" :: "r"(s), "l"(g) : "memory");
}
#define CP_COMMIT() asm volatile("cp.async.commit_group;" ::: "memory")
#define CP_WAIT(n)  asm volatile("cp.async.wait_group %0;" :: "n"(n) : "memory")

__device__ __forceinline__ void ldsm4(u32* r, u32 a) {
    asm volatile("ldmatrix.sync.aligned.m8n8.x4.shared.b16 {%0,%1,%2,%3}, [%4];"
                 : "=r"(r[0]), "=r"(r[1]), "=r"(r[2]), "=r"(r[3]) : "r"(a));
}
__device__ __forceinline__ void mma16816(float* c, const u32* a, const u32* b) {
    asm volatile(
        "mma.sync.aligned.m16n8k16.row.col.f32.f16.f16.f32 "
        "{%0,%1,%2,%3}, {%4,%5,%6,%7}, {%8,%9}, {%0,%1,%2,%3};"
        : "+f"(c[0]), "+f"(c[1]), "+f"(c[2]), "+f"(c[3])
        : "r"(a[0]), "r"(a[1]), "r"(a[2]), "r"(a[3]), "r"(b[0]), "r"(b[1]));
}

__device__ __forceinline__ u16 f16h(float v) {
    __half h = __float2half_rn(v);
    return *reinterpret_cast<u16*>(&h);
}
__device__ __forceinline__ void split_f16(float v, u16& h, u16& l) {
    __half hb = __float2half_rn(v);
    float hf = __half2float(hb);
    __half lb = __float2half_rn(v - hf);
    h = *reinterpret_cast<u16*>(&hb);
    l = *reinterpret_cast<u16*>(&lb);
}
__device__ __forceinline__ void split_pack(float a, float b, u32& ph, u32& pl) {
    u16 ha, la, hb, lb;
    split_f16(a, ha, la);
    split_f16(b, hb, lb);
    ph = (u32)ha | ((u32)hb << 16);
    pl = (u32)la | ((u32)lb << 16);
}
__device__ __forceinline__ u32 pack_h(float a, float b) {
    return (u32)f16h(a) | ((u32)f16h(b) << 16);
}

// ---------------------------------------------------------------------------
// RoPE cos/sin table
// ---------------------------------------------------------------------------
__global__ void __launch_bounds__(256)
rope_table()
{
    int idx = blockIdx.x * 256 + threadIdx.x;
    if (idx < NQ * 32) {
        int pos = idx >> 5, i = idx & 31;
        float inv = exp2f((float)i * NEG_L2B_32);
        float sn, cs;
        sincosf((float)pos * inv, &sn, &cs);
        g_cs[idx] = make_float2(cs, sn);
    }
}

// ---------------------------------------------------------------------------
// Transpose + fp16 split: in [rows, C] fp32 -> out [C][rows]; lo optional
// ---------------------------------------------------------------------------
__global__ void __launch_bounds__(256)
conv_split_T(const float* __restrict__ in, u16* __restrict__ oh,
             u16* __restrict__ ol, int R, int C, size_t in_bs, size_t out_bs)
{
    __shared__ float t[32][33];
    const float* ib = in + (size_t)blockIdx.z * in_bs;
    int x = blockIdx.x * 32 + threadIdx.x;
    int y0 = blockIdx.y * 32 + threadIdx.y;
    #pragma unroll
    for (int i = 0; i < 32; i += 8)
        t[threadIdx.y + i][threadIdx.x] = ib[(size_t)(y0 + i) * C + x];
    __syncthreads();
    int orow0 = blockIdx.x * 32 + threadIdx.y;
    int ocol  = blockIdx.y * 32 + threadIdx.x;
    #pragma unroll
    for (int i = 0; i < 32; i += 8) {
        float v = t[threadIdx.x][threadIdx.y + i];
        size_t o = (size_t)blockIdx.z * out_bs + (size_t)(orow0 + i) * R + ocol;
        if (ol) {
            u16 h, l;
            split_f16(v, h, l);
            oh[o] = h; ol[o] = l;
        } else {
            oh[o] = f16h(v);
        }
    }
}

__global__ void __launch_bounds__(256)
conv_split(const float* __restrict__ in, u16* __restrict__ oh,
           u16* __restrict__ ol, int n)
{
    int i = blockIdx.x * 256 + threadIdx.x;
    if (i < n) { u16 h, l; split_f16(in[i], h, l); oh[i] = h; ol[i] = l; }
}

// ---------------------------------------------------------------------------
// fp16 2-pass split GEMM: C[m,n] = sum_k A[m,k]*B[n,k]
// A: hi+lo fp16 (2-term), B: hi fp16 (1-term). 128x128 tile, BK=64,
// 8 warps (4m x 2n -> warp 32m x 64n), 3-stage cp.async.
// MODE 1: C[(bz*DQ+m)*NQ+n] = acc + Feat[..] + Bias[m]          (out proj)
// MODE 2: RoPE(m, n%64) -> g_qr hi/lo at [(bz*NQ+m)*DQ+n]       (q proj)
// MODE 3: n<768: RoPE K hi -> g_k[b,h,t,hd]; n>=768: V^T hi     (kv proj)
// ---------------------------------------------------------------------------
#define BK 64
#define STG 49152
#define AH_O 0
#define AL_O 16384
#define BH_O 32768
#define GSMEM (3*STG)

template<int MODE>
__global__ void __launch_bounds__(256)
gemm_mma(const u16* __restrict__ Ah, const u16* __restrict__ Al,
         const u16* __restrict__ Bh,
         float* __restrict__ C, const float* __restrict__ Feat,
         const float* __restrict__ Bias, int K, size_t sA, size_t sB)
{
    extern __shared__ char smdyn[];
    const u32 sbase = smem_u32(smdyn);
    const int tid  = threadIdx.x;
    const int lane = tid & 31;
    const int wid  = tid >> 5;
    const int wm   = (wid & 3) * 32;
    const int wn   = (wid >> 2) * 64;
    const int m0 = blockIdx.y * 128;
    const int n0 = blockIdx.x * 128;
    const int bz = blockIdx.z;
    const u16* Ahb = Ah + (size_t)bz * sA;
    const u16* Alb = Al + (size_t)bz * sA;
    const u16* Bhb = Bh + (size_t)bz * sB;

    float acc[2][8][4];
    #pragma unroll
    for (int i = 0; i < 2; i++)
        #pragma unroll
        for (int j = 0; j < 8; j++)
            #pragma unroll
            for (int p = 0; p < 4; p++) acc[i][j][p] = 0.f;

    const int KT = K / BK;

    #define LOAD_STAGE(kt, slot) do {                                           \
        u32 so_ = sbase + (u32)(slot) * STG;                                    \
        int k0_ = (kt) * BK;                                                    \
        _Pragma("unroll")                                                       \
        for (int i_ = 0; i_ < 4; i_++) {                                        \
            int chunk_ = i_ * 256 + tid;                                        \
            int row_ = chunk_ >> 3, c_ = chunk_ & 7;                            \
            u32 off_ = swz((u32)(row_ * 128 + c_ * 16));                        \
            size_t ga_ = (size_t)(m0 + row_) * K + k0_ + c_ * 8;                \
            size_t gb_ = (size_t)(n0 + row_) * K + k0_ + c_ * 8;                \
            cpa16(so_ + AH_O + off_, Ahb + ga_);                                \
            cpa16(so_ + AL_O + off_, Alb + ga_);                                \
            cpa16(so_ + BH_O + off_, Bhb + gb_);                                \
        }                                                                       \
    } while (0)

    LOAD_STAGE(0, 0);
    CP_COMMIT();
    if (KT > 1) { LOAD_STAGE(1, 1); CP_COMMIT(); }

    int slot = 0;
    for (int kt = 0; kt < KT; kt++) {
        if (kt + 1 < KT) CP_WAIT(1); else CP_WAIT(0);
        __syncthreads();
        if (kt + 2 < KT) {
            int ns = slot + 2; if (ns >= 3) ns -= 3;
            LOAD_STAGE(kt + 2, ns);
            CP_COMMIT();
        }
        const u32 sa = sbase + (u32)slot * STG;
        #pragma unroll
        for (int ks = 0; ks < 4; ks++) {
            u32 ahf[2][4], alf[2][4], bhf[8][2];
            #pragma unroll
            for (int mi = 0; mi < 2; mi++) {
                int row = wm + mi * 16 + (lane & 15);
                int chunk = 2 * ks + (lane >> 4);
                u32 off = swz((u32)(row * 128 + chunk * 16));
                ldsm4(ahf[mi], sa + AH_O + off);
                ldsm4(alf[mi], sa + AL_O + off);
            }
            #pragma unroll
            for (int jj = 0; jj < 4; jj++) {
                int g = lane >> 3;
                int row = wn + (2 * jj + (g >> 1)) * 8 + (lane & 7);
                int chunk = 2 * ks + (g & 1);
                u32 off = swz((u32)(row * 128 + chunk * 16));
                u32 t[4];
                ldsm4(t, sa + BH_O + off);
                bhf[2*jj][0] = t[0]; bhf[2*jj][1] = t[1];
                bhf[2*jj+1][0] = t[2]; bhf[2*jj+1][1] = t[3];
            }
            #pragma unroll
            for (int mi = 0; mi < 2; mi++)
                #pragma unroll
                for (int ni = 0; ni < 8; ni++) {
                    mma16816(acc[mi][ni], ahf[mi], bhf[ni]);
                    mma16816(acc[mi][ni], alf[mi], bhf[ni]);
                }
        }
        __syncthreads();
        slot++; if (slot >= 3) slot = 0;
    }

    // ---- epilogues ----
    if (MODE == 1) {
        #pragma unroll
        for (int mi = 0; mi < 2; mi++)
            #pragma unroll
            for (int ni = 0; ni < 8; ni++) {
                int m = m0 + wm + mi * 16 + (lane >> 2);
                int n = n0 + wn + ni * 8 + (lane & 3) * 2;
                const float* c = acc[mi][ni];
                size_t a0 = ((size_t)bz * DQ + m) * NQ + n;
                size_t a1 = ((size_t)bz * DQ + m + 8) * NQ + n;
                float b0 = Bias[m], b1 = Bias[m + 8];
                float2 f0 = *(const float2*)&Feat[a0];
                float2 f1 = *(const float2*)&Feat[a1];
                *(float2*)&C[a0] = make_float2(c[0] + f0.x + b0, c[1] + f0.y + b0);
                *(float2*)&C[a1] = make_float2(c[2] + f1.x + b1, c[3] + f1.y + b1);
            }
    } else if (MODE == 2) {
        #pragma unroll
        for (int mi = 0; mi < 2; mi++)
            #pragma unroll
            for (int ni = 0; ni < 4; ni++)
                #pragma unroll
                for (int half = 0; half < 2; half++) {
                    int m = m0 + wm + mi * 16 + (lane >> 2) + half * 8;
                    int i0 = ni * 8 + (lane & 3) * 2;       // i_loc in [0,32)
                    float2 cs0 = g_cs[m * 32 + i0];
                    float2 cs1 = g_cs[m * 32 + i0 + 1];
                    float x1a = acc[mi][ni][half*2],   x2a = acc[mi][ni+4][half*2];
                    float x1b = acc[mi][ni][half*2+1], x2b = acc[mi][ni+4][half*2+1];
                    float y1a = x1a * cs0.x - x2a * cs0.y;
                    float y2a = x2a * cs0.x + x1a * cs0.y;
                    float y1b = x1b * cs1.x - x2b * cs1.y;
                    float y2b = x2b * cs1.x + x1b * cs1.y;
                    int n = n0 + wn + i0;
                    size_t base = ((size_t)bz * NQ + m) * DQ;
                    u32 ph, pl;
                    split_pack(y1a, y1b, ph, pl);
                    *(u32*)&g_qr_h[base + n] = ph;
                    *(u32*)&g_qr_l[base + n] = pl;
                    split_pack(y2a, y2b, ph, pl);
                    *(u32*)&g_qr_h[base + n + 32] = ph;
                    *(u32*)&g_qr_l[base + n + 32] = pl;
                }
    } else { // MODE 3 : kv
        if (n0 + wn < DQ) {
            // K half with RoPE (hi only)
            #pragma unroll
            for (int mi = 0; mi < 2; mi++)
                #pragma unroll
                for (int ni = 0; ni < 4; ni++)
                    #pragma unroll
                    for (int half = 0; half < 2; half++) {
                        int m = m0 + wm + mi * 16 + (lane >> 2) + half * 8;
                        int bb = m >> 6, t = m & 63;
                        int n = n0 + wn + ni * 8 + (lane & 3) * 2;
                        int h = n >> 6;
                        int i0 = n & 63;                    // < 32
                        float2 cs0 = g_cs[t * 32 + i0];
                        float2 cs1 = g_cs[t * 32 + i0 + 1];
                        float x1a = acc[mi][ni][half*2],   x2a = acc[mi][ni+4][half*2];
                        float x1b = acc[mi][ni][half*2+1], x2b = acc[mi][ni+4][half*2+1];
                        float y1a = x1a * cs0.x - x2a * cs0.y;
                        float y2a = x2a * cs0.x + x1a * cs0.y;
                        float y1b = x1b * cs1.x - x2b * cs1.y;
                        float y2b = x2b * cs1.x + x1b * cs1.y;
                        size_t base = (((size_t)bb * NH + h) * NT + t) * HD;
                        *(u32*)&g_k_h[base + i0]      = pack_h(y1a, y1b);
                        *(u32*)&g_k_h[base + i0 + 32] = pack_h(y2a, y2b);
                    }
        } else {
            // V half, store transposed [b,h,hd,t] (hi only)
            #pragma unroll
            for (int mi = 0; mi < 2; mi++)
                #pragma unroll
                for (int ni = 0; ni < 8; ni++)
                    #pragma unroll
                    for (int p = 0; p < 4; p++) {
                        int m = m0 + wm + mi * 16 + (lane >> 2) + (p >> 1) * 8;
                        int bb = m >> 6, t = m & 63;
                        int n = n0 + wn + ni * 8 + (lane & 3) * 2 + (p & 1);
                        int h = (n - DQ) >> 6;
                        int hd = n & 63;
                        size_t o = (((size_t)bb * NH + h) * HD + hd) * NT + t;
                        g_vT_h[o] = f16h(acc[mi][ni][p]);
                    }
        }
    }
    #undef LOAD_STAGE
}

// ---------------------------------------------------------------------------
// Tensor-core attention: grid (NQ/128, NH, BATCH), 128 threads (4 warps).
// Q hi/lo fp16 (2-term), K/V hi fp16 (1-term). Softmax+P split in registers.
// ---------------------------------------------------------------------------
#define AQH 0
#define AQL 16384
#define AKH 32768
#define AVH 40960
#define ASMEM 49152

__global__ void __launch_bounds__(128)
attn_tc()
{
    extern __shared__ char smdyn[];
    const u32 sbase = smem_u32(smdyn);
    const int tid  = threadIdx.x;
    const int lane = tid & 31;
    const int wid  = tid >> 5;
    const int q0 = blockIdx.x * 128;
    const int h  = blockIdx.y;
    const int b  = blockIdx.z;

    {
        const u16* qh = g_qr_h + ((size_t)(b * NQ + q0)) * DQ + h * HD;
        const u16* ql = g_qr_l + ((size_t)(b * NQ + q0)) * DQ + h * HD;
        #pragma unroll
        for (int i = 0; i < 8; i++) {
            int c = i * 128 + tid;
            int row = c >> 3, cc = c & 7;
            u32 off = swz((u32)(row * 128 + cc * 16));
            cpa16(sbase + AQH + off, qh + (size_t)row * DQ + cc * 8);
            cpa16(sbase + AQL + off, ql + (size_t)row * DQ + cc * 8);
        }
        size_t kvb = ((size_t)b * NH + h) * (NT * HD);
        #pragma unroll
        for (int i = 0; i < 4; i++) {
            int c = i * 128 + tid;
            int row = c >> 3, cc = c & 7;
            u32 off = swz((u32)(row * 128 + cc * 16));
            cpa16(sbase + AKH + off, g_k_h  + kvb + row * 64 + cc * 8);
            cpa16(sbase + AVH + off, g_vT_h + kvb + row * 64 + cc * 8);
        }
        CP_COMMIT();
        CP_WAIT(0);
        __syncthreads();
    }

    // S = Q K^T (2-pass split)
    float s[2][8][4];
    #pragma unroll
    for (int i = 0; i < 2; i++)
        #pragma unroll
        for (int j = 0; j < 8; j++)
            #pragma unroll
            for (int p = 0; p < 4; p++) s[i][j][p] = 0.f;

    #pragma unroll
    for (int ks = 0; ks < 4; ks++) {
        u32 aqh[2][4], aql[2][4], bkh[8][2];
        #pragma unroll
        for (int mi = 0; mi < 2; mi++) {
            int row = wid * 32 + mi * 16 + (lane & 15);
            int chunk = 2 * ks + (lane >> 4);
            u32 off = swz((u32)(row * 128 + chunk * 16));
            ldsm4(aqh[mi], sbase + AQH + off);
            ldsm4(aql[mi], sbase + AQL + off);
        }
        #pragma unroll
        for (int jj = 0; jj < 4; jj++) {
            int g = lane >> 3;
            int row = (2 * jj + (g >> 1)) * 8 + (lane & 7);
            int chunk = 2 * ks + (g & 1);
            u32 off = swz((u32)(row * 128 + chunk * 16));
            u32 t[4];
            ldsm4(t, sbase + AKH + off);
            bkh[2*jj][0] = t[0]; bkh[2*jj][1] = t[1];
            bkh[2*jj+1][0] = t[2]; bkh[2*jj+1][1] = t[3];
        }
        #pragma unroll
        for (int mi = 0; mi < 2; mi++)
            #pragma unroll
            for (int ni = 0; ni < 8; ni++) {
                mma16816(s[mi][ni], aqh[mi], bkh[ni]);
                mma16816(s[mi][ni], aql[mi], bkh[ni]);
            }
    }

    // softmax (scale 1/8)
    #pragma unroll
    for (int mi = 0; mi < 2; mi++) {
        float mx0 = -1e30f, mx1 = -1e30f;
        #pragma unroll
        for (int ni = 0; ni < 8; ni++) {
            #pragma unroll
            for (int p = 0; p < 4; p++) s[mi][ni][p] *= 0.125f;
            mx0 = fmaxf(mx0, fmaxf(s[mi][ni][0], s[mi][ni][1]));
            mx1 = fmaxf(mx1, fmaxf(s[mi][ni][2], s[mi][ni][3]));
        }
        mx0 = fmaxf(mx0, __shfl_xor_sync(0xffffffffu, mx0, 1));
        mx0 = fmaxf(mx0, __shfl_xor_sync(0xffffffffu, mx0, 2));
        mx1 = fmaxf(mx1, __shfl_xor_sync(0xffffffffu, mx1, 1));
        mx1 = fmaxf(mx1, __shfl_xor_sync(0xffffffffu, mx1, 2));
        float sm0 = 0.f, sm1 = 0.f;
        #pragma unroll
        for (int ni = 0; ni < 8; ni++) {
            s[mi][ni][0] = __expf(s[mi][ni][0] - mx0);
            s[mi][ni][1] = __expf(s[mi][ni][1] - mx0);
            s[mi][ni][2] = __expf(s[mi][ni][2] - mx1);
            s[mi][ni][3] = __expf(s[mi][ni][3] - mx1);
            sm0 += s[mi][ni][0] + s[mi][ni][1];
            sm1 += s[mi][ni][2] + s[mi][ni][3];
        }
        sm0 += __shfl_xor_sync(0xffffffffu, sm0, 1);
        sm0 += __shfl_xor_sync(0xffffffffu, sm0, 2);
        sm1 += __shfl_xor_sync(0xffffffffu, sm1, 1);
        sm1 += __shfl_xor_sync(0xffffffffu, sm1, 2);
        float i0 = 1.f / sm0, i1 = 1.f / sm1;
        #pragma unroll
        for (int ni = 0; ni < 8; ni++) {
            s[mi][ni][0] *= i0; s[mi][ni][1] *= i0;
            s[mi][ni][2] *= i1; s[mi][ni][3] *= i1;
        }
    }

    // O = P V (P 2-term fp16 from registers)
    float o[2][8][4];
    #pragma unroll
    for (int i = 0; i < 2; i++)
        #pragma unroll
        for (int j = 0; j < 8; j++)
            #pragma unroll
            for (int p = 0; p < 4; p++) o[i][j][p] = 0.f;

    #pragma unroll
    for (int kc = 0; kc < 4; kc++) {
        u32 pah[2][4], pal[2][4], bvh[8][2];
        #pragma unroll
        for (int mi = 0; mi < 2; mi++) {
            split_pack(s[mi][2*kc][0],   s[mi][2*kc][1],   pah[mi][0], pal[mi][0]);
            split_pack(s[mi][2*kc][2],   s[mi][2*kc][3],   pah[mi][1], pal[mi][1]);
            split_pack(s[mi][2*kc+1][0], s[mi][2*kc+1][1], pah[mi][2], pal[mi][2]);
            split_pack(s[mi][2*kc+1][2], s[mi][2*kc+1][3], pah[mi][3], pal[mi][3]);
        }
        #pragma unroll
        for (int jj = 0; jj < 4; jj++) {
            int g = lane >> 3;
            int row = (2 * jj + (g >> 1)) * 8 + (lane & 7);
            int chunk = 2 * kc + (g & 1);
            u32 off = swz((u32)(row * 128 + chunk * 16));
            u32 t[4];
            ldsm4(t, sbase + AVH + off);
            bvh[2*jj][0] = t[0]; bvh[2*jj][1] = t[1];
            bvh[2*jj+1][0] = t[2]; bvh[2*jj+1][1] = t[3];
        }
        #pragma unroll
        for (int mi = 0; mi < 2; mi++)
            #pragma unroll
            for (int ni = 0; ni < 8; ni++) {
                mma16816(o[mi][ni], pah[mi], bvh[ni]);
                mma16816(o[mi][ni], pal[mi], bvh[ni]);
            }
    }

    // store O hi fp16 at [B,Nq,Dq]
    #pragma unroll
    for (int mi = 0; mi < 2; mi++)
        #pragma unroll
        for (int ni = 0; ni < 8; ni++) {
            int q = q0 + wid * 32 + mi * 16 + (lane >> 2);
            int col = h * HD + ni * 8 + (lane & 3) * 2;
            size_t a0 = ((size_t)(b * NQ + q)) * DQ + col;
            size_t a1 = ((size_t)(b * NQ + q + 8)) * DQ + col;
            *(u32*)&g_o_h[a0] = pack_h(o[mi][ni][0], o[mi][ni][1]);
            *(u32*)&g_o_h[a1] = pack_h(o[mi][ni][2], o[mi][ni][3]);
        }
}

// ---------------------------------------------------------------------------
// Launch
// ---------------------------------------------------------------------------
extern "C" void kernel_launch(void* const* d_in, const int* in_sizes, int n_in,
                              void* d_out, int out_size)
{
    (void)in_sizes; (void)n_in; (void)out_size;
    const float* feat   = (const float*)d_in[0];
    const float* tokens = (const float*)d_in[1];
    const float* Wq     = (const float*)d_in[2];
    const float* Wkv    = (const float*)d_in[3];
    const float* Wout   = (const float*)d_in[4];
    const float* bout   = (const float*)d_in[5];
    float* outp = (float*)d_out;

    u16 *pqih, *pqil, *pwqh, *pwkh, *pwoh, *pwol, *pth, *ptl, *poh;
    cudaGetSymbolAddress((void**)&pqih, g_qin_h);
    cudaGetSymbolAddress((void**)&pqil, g_qin_l);
    cudaGetSymbolAddress((void**)&pwqh, g_wq_h);
    cudaGetSymbolAddress((void**)&pwkh, g_wkv_h);
    cudaGetSymbolAddress((void**)&pwoh, g_wo_h);
    cudaGetSymbolAddress((void**)&pwol, g_wo_l);
    cudaGetSymbolAddress((void**)&pth,  g_tok_h);
    cudaGetSymbolAddress((void**)&ptl,  g_tok_l);
    cudaGetSymbolAddress((void**)&poh,  g_o_h);

    cudaFuncSetAttribute(gemm_mma<1>, cudaFuncAttributeMaxDynamicSharedMemorySize, GSMEM);
    cudaFuncSetAttribute(gemm_mma<2>, cudaFuncAttributeMaxDynamicSharedMemorySize, GSMEM);
    cudaFuncSetAttribute(gemm_mma<3>, cudaFuncAttributeMaxDynamicSharedMemorySize, GSMEM);
    cudaFuncSetAttribute(attn_tc,     cudaFuncAttributeMaxDynamicSharedMemorySize, ASMEM);

    rope_table<<<(NQ*32 + 255)/256, 256>>>();

    conv_split_T<<<dim3(NQ/32, DQ/32, BATCH), dim3(32, 8)>>>(
        feat, pqih, pqil, DQ, NQ, (size_t)DQ*NQ, (size_t)NQ*DQ);
    conv_split_T<<<dim3(DQ/32, DQ/32, 1), dim3(32, 8)>>>(Wq,   pwqh, nullptr, DQ,  DQ,   0, 0);
    conv_split_T<<<dim3(DKV2/32, DKV/32, 1), dim3(32, 8)>>>(Wkv, pwkh, nullptr, DKV, DKV2, 0, 0);
    conv_split_T<<<dim3(DQ/32, DQ/32, 1), dim3(32, 8)>>>(Wout, pwoh, pwol, DQ,  DQ,   0, 0);
    conv_split<<<(NKV*DKV + 255)/256, 256>>>(tokens, pth, ptl, NKV*DKV);

    // kv = tokens @ Wkv -> RoPE'd K hi + transposed V hi
    gemm_mma<3><<<dim3(DKV2/128, NKV/128, 1), 256, GSMEM>>>(
        pth, ptl, pwkh, nullptr, nullptr, nullptr, DKV, 0, 0);

    // q = q_in @ Wq -> RoPE'd q hi/lo
    gemm_mma<2><<<dim3(DQ/128, NQ/128, BATCH), 256, GSMEM>>>(
        pqih, pqil, pwqh, nullptr, nullptr, nullptr, DQ, (size_t)NQ*DQ, 0);

    // attention (tensor cores)
    attn_tc<<<dim3(NQ/128, NH, BATCH), 128, ASMEM>>>();

    // out[d,q] = feat + (o @ Wout)^T + bout ; A = WoutT hi/lo, B = o hi
    gemm_mma<1><<<dim3(NQ/128, DQ/128, BATCH), 256, GSMEM>>>(
        pwoh, pwol, poh, outp, feat, bout, DQ, 0, (size_t)NQ*DQ);
}

// round 6
// speedup vs baseline: 7.8122x; 1.6274x over previous
#include <cuda_runtime.h>
#include <cuda_fp16.h>
#include <math.h>

// Problem constants
#define BATCH 16
#define DQ    768
#define NQ    1024
#define NT    64
#define DKV   384
#define NH    12
#define HD    64
#define NKV   (BATCH*NT)
#define DKV2  (2*DQ)

#define NEG_L2B_32 (-0.41524101186091903f)   // -log2(10000)/32

typedef unsigned short u16;
typedef unsigned int   u32;

// ---------------------------------------------------------------------------
// Scratch (device globals)
// ---------------------------------------------------------------------------
__device__ __align__(16) u16 g_qin_h[(size_t)BATCH*NQ*DQ];  // feat^T hi fp16
__device__ __align__(16) u16 g_qr_h [(size_t)BATCH*NQ*DQ];  // rope'd q hi/lo
__device__ __align__(16) u16 g_qr_l [(size_t)BATCH*NQ*DQ];
__device__ __align__(16) u16 g_k_h  [(size_t)BATCH*NH*NT*HD];  // rope'd K hi [b,h,t,hd]
__device__ __align__(16) u16 g_vT_h [(size_t)BATCH*NH*HD*NT];  // V^T hi [b,h,hd,t]
__device__ __align__(16) u16 g_o_h  [(size_t)BATCH*NQ*DQ];  // attn out hi [B,Nq,Dq]
__device__ __align__(16) u16 g_wq_h [DQ*DQ];                // WqT hi
__device__ __align__(16) u16 g_wkv_h[DKV2*DKV];             // WkvT hi
__device__ __align__(16) u16 g_wo_h [DQ*DQ];                // WoutT hi
__device__ __align__(16) u16 g_tok_h[NKV*DKV];              // tokens hi
__device__ __align__(16) float2 g_cs[NQ*32];                // (cos, sin)

// ---------------------------------------------------------------------------
// Helpers (base-ISA only)
// ---------------------------------------------------------------------------
__device__ __forceinline__ u32 smem_u32(const void* p) {
    u32 a;
    asm("{ .reg .u64 t; cvta.to.shared.u64 t, %1; cvt.u32.u64 %0, t; }" : "=r"(a) : "l"(p));
    return a;
}
__device__ __forceinline__ u32 swz(u32 o) { return o ^ ((o >> 3) & 0x70); }

__device__ __forceinline__ void cpa16(u32 s, const void* g) {
    asm volatile("cp.async.cg.shared.global [%0], [%1], 16;" :: "r"(s), "l"(g) : "memory");
}
#define CP_COMMIT() asm volatile("cp.async.commit_group;" ::: "memory")
#define CP_WAIT(n)  asm volatile("cp.async.wait_group %0;" :: "n"(n) : "memory")

__device__ __forceinline__ void ldsm4(u32* r, u32 a) {
    asm volatile("ldmatrix.sync.aligned.m8n8.x4.shared.b16 {%0,%1,%2,%3}, [%4];"
                 : "=r"(r[0]), "=r"(r[1]), "=r"(r[2]), "=r"(r[3]) : "r"(a));
}
__device__ __forceinline__ void mma16816(float* c, const u32* a, const u32* b) {
    asm volatile(
        "mma.sync.aligned.m16n8k16.row.col.f32.f16.f16.f32 "
        "{%0,%1,%2,%3}, {%4,%5,%6,%7}, {%8,%9}, {%0,%1,%2,%3};"
        : "+f"(c[0]), "+f"(c[1]), "+f"(c[2]), "+f"(c[3])
        : "r"(a[0]), "r"(a[1]), "r"(a[2]), "r"(a[3]), "r"(b[0]), "r"(b[1]));
}

__device__ __forceinline__ u16 f16h(float v) {
    __half h = __float2half_rn(v);
    return *reinterpret_cast<u16*>(&h);
}
__device__ __forceinline__ void split_f16(float v, u16& h, u16& l) {
    __half hb = __float2half_rn(v);
    float hf = __half2float(hb);
    __half lb = __float2half_rn(v - hf);
    h = *reinterpret_cast<u16*>(&hb);
    l = *reinterpret_cast<u16*>(&lb);
}
__device__ __forceinline__ void split_pack(float a, float b, u32& ph, u32& pl) {
    u16 ha, la, hb, lb;
    split_f16(a, ha, la);
    split_f16(b, hb, lb);
    ph = (u32)ha | ((u32)hb << 16);
    pl = (u32)la | ((u32)lb << 16);
}
__device__ __forceinline__ u32 pack_h(float a, float b) {
    return (u32)f16h(a) | ((u32)f16h(b) << 16);
}

// ---------------------------------------------------------------------------
// RoPE cos/sin table
// ---------------------------------------------------------------------------
__global__ void __launch_bounds__(256)
rope_table()
{
    int idx = blockIdx.x * 256 + threadIdx.x;
    if (idx < NQ * 32) {
        int pos = idx >> 5, i = idx & 31;
        float inv = exp2f((float)i * NEG_L2B_32);
        float sn, cs;
        sincosf((float)pos * inv, &sn, &cs);
        g_cs[idx] = make_float2(cs, sn);
    }
}

// ---------------------------------------------------------------------------
// Transpose + fp16 convert: in [rows, C] fp32 -> out [C][rows] hi
// ---------------------------------------------------------------------------
__global__ void __launch_bounds__(256)
conv_T(const float* __restrict__ in, u16* __restrict__ oh,
       int R, int C, size_t in_bs, size_t out_bs)
{
    __shared__ float t[32][33];
    const float* ib = in + (size_t)blockIdx.z * in_bs;
    int x = blockIdx.x * 32 + threadIdx.x;
    int y0 = blockIdx.y * 32 + threadIdx.y;
    #pragma unroll
    for (int i = 0; i < 32; i += 8)
        t[threadIdx.y + i][threadIdx.x] = ib[(size_t)(y0 + i) * C + x];
    __syncthreads();
    int orow0 = blockIdx.x * 32 + threadIdx.y;
    int ocol  = blockIdx.y * 32 + threadIdx.x;
    #pragma unroll
    for (int i = 0; i < 32; i += 8) {
        float v = t[threadIdx.x][threadIdx.y + i];
        size_t o = (size_t)blockIdx.z * out_bs + (size_t)(orow0 + i) * R + ocol;
        oh[o] = f16h(v);
    }
}

__global__ void __launch_bounds__(256)
conv_lin(const float* __restrict__ in, u16* __restrict__ oh, int n)
{
    int i = blockIdx.x * 256 + threadIdx.x;
    if (i < n) oh[i] = f16h(in[i]);
}

// ---------------------------------------------------------------------------
// Pure fp16 1-pass GEMM: C[m,n] = sum_k A[m,k]*B[n,k], K-major fp16 operands.
// 128x128 tile, BK=64, 8 warps (4m x 2n -> warp 32m x 64n), 3-stage cp.async,
// 2 CTAs/SM.
// MODE 1: C[(bz*DQ+m)*NQ+n] = acc + Feat[..] + Bias[m]          (out proj)
// MODE 2: RoPE(m, n%64) -> g_qr hi/lo at [(bz*NQ+m)*DQ+n]       (q proj)
// MODE 3: n<768: RoPE K hi -> g_k[b,h,t,hd]; n>=768: V^T hi     (kv proj)
// ---------------------------------------------------------------------------
#define BK 64
#define STG 32768
#define AH_O 0
#define BH_O 16384
#define GSMEM (3*STG)

template<int MODE>
__global__ void __launch_bounds__(256, 2)
gemm_mma(const u16* __restrict__ Ah, const u16* __restrict__ Bh,
         float* __restrict__ C, const float* __restrict__ Feat,
         const float* __restrict__ Bias, int K, size_t sA, size_t sB)
{
    extern __shared__ char smdyn[];
    const u32 sbase = smem_u32(smdyn);
    const int tid  = threadIdx.x;
    const int lane = tid & 31;
    const int wid  = tid >> 5;
    const int wm   = (wid & 3) * 32;
    const int wn   = (wid >> 2) * 64;
    const int m0 = blockIdx.y * 128;
    const int n0 = blockIdx.x * 128;
    const int bz = blockIdx.z;
    const u16* Ahb = Ah + (size_t)bz * sA;
    const u16* Bhb = Bh + (size_t)bz * sB;

    float acc[2][8][4];
    #pragma unroll
    for (int i = 0; i < 2; i++)
        #pragma unroll
        for (int j = 0; j < 8; j++)
            #pragma unroll
            for (int p = 0; p < 4; p++) acc[i][j][p] = 0.f;

    const int KT = K / BK;

    #define LOAD_STAGE(kt, slot) do {                                           \
        u32 so_ = sbase + (u32)(slot) * STG;                                    \
        int k0_ = (kt) * BK;                                                    \
        _Pragma("unroll")                                                       \
        for (int i_ = 0; i_ < 4; i_++) {                                        \
            int chunk_ = i_ * 256 + tid;                                        \
            int row_ = chunk_ >> 3, c_ = chunk_ & 7;                            \
            u32 off_ = swz((u32)(row_ * 128 + c_ * 16));                        \
            size_t ga_ = (size_t)(m0 + row_) * K + k0_ + c_ * 8;                \
            size_t gb_ = (size_t)(n0 + row_) * K + k0_ + c_ * 8;                \
            cpa16(so_ + AH_O + off_, Ahb + ga_);                                \
            cpa16(so_ + BH_O + off_, Bhb + gb_);                                \
        }                                                                       \
    } while (0)

    LOAD_STAGE(0, 0);
    CP_COMMIT();
    if (KT > 1) { LOAD_STAGE(1, 1); CP_COMMIT(); }

    int slot = 0;
    for (int kt = 0; kt < KT; kt++) {
        if (kt + 1 < KT) CP_WAIT(1); else CP_WAIT(0);
        __syncthreads();
        if (kt + 2 < KT) {
            int ns = slot + 2; if (ns >= 3) ns -= 3;
            LOAD_STAGE(kt + 2, ns);
            CP_COMMIT();
        }
        const u32 sa = sbase + (u32)slot * STG;
        #pragma unroll
        for (int ks = 0; ks < 4; ks++) {
            u32 ahf[2][4], bhf[8][2];
            #pragma unroll
            for (int mi = 0; mi < 2; mi++) {
                int row = wm + mi * 16 + (lane & 15);
                int chunk = 2 * ks + (lane >> 4);
                u32 off = swz((u32)(row * 128 + chunk * 16));
                ldsm4(ahf[mi], sa + AH_O + off);
            }
            #pragma unroll
            for (int jj = 0; jj < 4; jj++) {
                int g = lane >> 3;
                int row = wn + (2 * jj + (g >> 1)) * 8 + (lane & 7);
                int chunk = 2 * ks + (g & 1);
                u32 off = swz((u32)(row * 128 + chunk * 16));
                u32 t[4];
                ldsm4(t, sa + BH_O + off);
                bhf[2*jj][0] = t[0]; bhf[2*jj][1] = t[1];
                bhf[2*jj+1][0] = t[2]; bhf[2*jj+1][1] = t[3];
            }
            #pragma unroll
            for (int mi = 0; mi < 2; mi++)
                #pragma unroll
                for (int ni = 0; ni < 8; ni++)
                    mma16816(acc[mi][ni], ahf[mi], bhf[ni]);
        }
        __syncthreads();
        slot++; if (slot >= 3) slot = 0;
    }

    // ---- epilogues ----
    if (MODE == 1) {
        #pragma unroll
        for (int mi = 0; mi < 2; mi++)
            #pragma unroll
            for (int ni = 0; ni < 8; ni++) {
                int m = m0 + wm + mi * 16 + (lane >> 2);
                int n = n0 + wn + ni * 8 + (lane & 3) * 2;
                const float* c = acc[mi][ni];
                size_t a0 = ((size_t)bz * DQ + m) * NQ + n;
                size_t a1 = ((size_t)bz * DQ + m + 8) * NQ + n;
                float b0 = Bias[m], b1 = Bias[m + 8];
                float2 f0 = *(const float2*)&Feat[a0];
                float2 f1 = *(const float2*)&Feat[a1];
                *(float2*)&C[a0] = make_float2(c[0] + f0.x + b0, c[1] + f0.y + b0);
                *(float2*)&C[a1] = make_float2(c[2] + f1.x + b1, c[3] + f1.y + b1);
            }
    } else if (MODE == 2) {
        #pragma unroll
        for (int mi = 0; mi < 2; mi++)
            #pragma unroll
            for (int ni = 0; ni < 4; ni++)
                #pragma unroll
                for (int half = 0; half < 2; half++) {
                    int m = m0 + wm + mi * 16 + (lane >> 2) + half * 8;
                    int i0 = ni * 8 + (lane & 3) * 2;       // i_loc in [0,32)
                    float2 cs0 = g_cs[m * 32 + i0];
                    float2 cs1 = g_cs[m * 32 + i0 + 1];
                    float x1a = acc[mi][ni][half*2],   x2a = acc[mi][ni+4][half*2];
                    float x1b = acc[mi][ni][half*2+1], x2b = acc[mi][ni+4][half*2+1];
                    float y1a = x1a * cs0.x - x2a * cs0.y;
                    float y2a = x2a * cs0.x + x1a * cs0.y;
                    float y1b = x1b * cs1.x - x2b * cs1.y;
                    float y2b = x2b * cs1.x + x1b * cs1.y;
                    int n = n0 + wn + i0;
                    size_t base = ((size_t)bz * NQ + m) * DQ;
                    u32 ph, pl;
                    split_pack(y1a, y1b, ph, pl);
                    *(u32*)&g_qr_h[base + n] = ph;
                    *(u32*)&g_qr_l[base + n] = pl;
                    split_pack(y2a, y2b, ph, pl);
                    *(u32*)&g_qr_h[base + n + 32] = ph;
                    *(u32*)&g_qr_l[base + n + 32] = pl;
                }
    } else { // MODE 3 : kv
        if (n0 + wn < DQ) {
            // K half with RoPE (hi only)
            #pragma unroll
            for (int mi = 0; mi < 2; mi++)
                #pragma unroll
                for (int ni = 0; ni < 4; ni++)
                    #pragma unroll
                    for (int half = 0; half < 2; half++) {
                        int m = m0 + wm + mi * 16 + (lane >> 2) + half * 8;
                        int bb = m >> 6, t = m & 63;
                        int n = n0 + wn + ni * 8 + (lane & 3) * 2;
                        int h = n >> 6;
                        int i0 = n & 63;                    // < 32
                        float2 cs0 = g_cs[t * 32 + i0];
                        float2 cs1 = g_cs[t * 32 + i0 + 1];
                        float x1a = acc[mi][ni][half*2],   x2a = acc[mi][ni+4][half*2];
                        float x1b = acc[mi][ni][half*2+1], x2b = acc[mi][ni+4][half*2+1];
                        float y1a = x1a * cs0.x - x2a * cs0.y;
                        float y2a = x2a * cs0.x + x1a * cs0.y;
                        float y1b = x1b * cs1.x - x2b * cs1.y;
                        float y2b = x2b * cs1.x + x1b * cs1.y;
                        size_t base = (((size_t)bb * NH + h) * NT + t) * HD;
                        *(u32*)&g_k_h[base + i0]      = pack_h(y1a, y1b);
                        *(u32*)&g_k_h[base + i0 + 32] = pack_h(y2a, y2b);
                    }
        } else {
            // V half, store transposed [b,h,hd,t] (hi only)
            #pragma unroll
            for (int mi = 0; mi < 2; mi++)
                #pragma unroll
                for (int ni = 0; ni < 8; ni++)
                    #pragma unroll
                    for (int p = 0; p < 4; p++) {
                        int m = m0 + wm + mi * 16 + (lane >> 2) + (p >> 1) * 8;
                        int bb = m >> 6, t = m & 63;
                        int n = n0 + wn + ni * 8 + (lane & 3) * 2 + (p & 1);
                        int h = (n - DQ) >> 6;
                        int hd = n & 63;
                        size_t o = (((size_t)bb * NH + h) * HD + hd) * NT + t;
                        g_vT_h[o] = f16h(acc[mi][ni][p]);
                    }
        }
    }
    #undef LOAD_STAGE
}

// ---------------------------------------------------------------------------
// Tensor-core attention: grid (NQ/128, NH, BATCH), 128 threads (4 warps).
// Q hi/lo fp16 (2-term), K/V hi fp16 (1-term). Softmax+P split in registers.
// ---------------------------------------------------------------------------
#define AQH 0
#define AQL 16384
#define AKH 32768
#define AVH 40960
#define ASMEM 49152

__global__ void __launch_bounds__(128)
attn_tc()
{
    extern __shared__ char smdyn[];
    const u32 sbase = smem_u32(smdyn);
    const int tid  = threadIdx.x;
    const int lane = tid & 31;
    const int wid  = tid >> 5;
    const int q0 = blockIdx.x * 128;
    const int h  = blockIdx.y;
    const int b  = blockIdx.z;

    {
        const u16* qh = g_qr_h + ((size_t)(b * NQ + q0)) * DQ + h * HD;
        const u16* ql = g_qr_l + ((size_t)(b * NQ + q0)) * DQ + h * HD;
        #pragma unroll
        for (int i = 0; i < 8; i++) {
            int c = i * 128 + tid;
            int row = c >> 3, cc = c & 7;
            u32 off = swz((u32)(row * 128 + cc * 16));
            cpa16(sbase + AQH + off, qh + (size_t)row * DQ + cc * 8);
            cpa16(sbase + AQL + off, ql + (size_t)row * DQ + cc * 8);
        }
        size_t kvb = ((size_t)b * NH + h) * (NT * HD);
        #pragma unroll
        for (int i = 0; i < 4; i++) {
            int c = i * 128 + tid;
            int row = c >> 3, cc = c & 7;
            u32 off = swz((u32)(row * 128 + cc * 16));
            cpa16(sbase + AKH + off, g_k_h  + kvb + row * 64 + cc * 8);
            cpa16(sbase + AVH + off, g_vT_h + kvb + row * 64 + cc * 8);
        }
        CP_COMMIT();
        CP_WAIT(0);
        __syncthreads();
    }

    // S = Q K^T (2-pass split)
    float s[2][8][4];
    #pragma unroll
    for (int i = 0; i < 2; i++)
        #pragma unroll
        for (int j = 0; j < 8; j++)
            #pragma unroll
            for (int p = 0; p < 4; p++) s[i][j][p] = 0.f;

    #pragma unroll
    for (int ks = 0; ks < 4; ks++) {
        u32 aqh[2][4], aql[2][4], bkh[8][2];
        #pragma unroll
        for (int mi = 0; mi < 2; mi++) {
            int row = wid * 32 + mi * 16 + (lane & 15);
            int chunk = 2 * ks + (lane >> 4);
            u32 off = swz((u32)(row * 128 + chunk * 16));
            ldsm4(aqh[mi], sbase + AQH + off);
            ldsm4(aql[mi], sbase + AQL + off);
        }
        #pragma unroll
        for (int jj = 0; jj < 4; jj++) {
            int g = lane >> 3;
            int row = (2 * jj + (g >> 1)) * 8 + (lane & 7);
            int chunk = 2 * ks + (g & 1);
            u32 off = swz((u32)(row * 128 + chunk * 16));
            u32 t[4];
            ldsm4(t, sbase + AKH + off);
            bkh[2*jj][0] = t[0]; bkh[2*jj][1] = t[1];
            bkh[2*jj+1][0] = t[2]; bkh[2*jj+1][1] = t[3];
        }
        #pragma unroll
        for (int mi = 0; mi < 2; mi++)
            #pragma unroll
            for (int ni = 0; ni < 8; ni++) {
                mma16816(s[mi][ni], aqh[mi], bkh[ni]);
                mma16816(s[mi][ni], aql[mi], bkh[ni]);
            }
    }

    // softmax (scale 1/8)
    #pragma unroll
    for (int mi = 0; mi < 2; mi++) {
        float mx0 = -1e30f, mx1 = -1e30f;
        #pragma unroll
        for (int ni = 0; ni < 8; ni++) {
            #pragma unroll
            for (int p = 0; p < 4; p++) s[mi][ni][p] *= 0.125f;
            mx0 = fmaxf(mx0, fmaxf(s[mi][ni][0], s[mi][ni][1]));
            mx1 = fmaxf(mx1, fmaxf(s[mi][ni][2], s[mi][ni][3]));
        }
        mx0 = fmaxf(mx0, __shfl_xor_sync(0xffffffffu, mx0, 1));
        mx0 = fmaxf(mx0, __shfl_xor_sync(0xffffffffu, mx0, 2));
        mx1 = fmaxf(mx1, __shfl_xor_sync(0xffffffffu, mx1, 1));
        mx1 = fmaxf(mx1, __shfl_xor_sync(0xffffffffu, mx1, 2));
        float sm0 = 0.f, sm1 = 0.f;
        #pragma unroll
        for (int ni = 0; ni < 8; ni++) {
            s[mi][ni][0] = __expf(s[mi][ni][0] - mx0);
            s[mi][ni][1] = __expf(s[mi][ni][1] - mx0);
            s[mi][ni][2] = __expf(s[mi][ni][2] - mx1);
            s[mi][ni][3] = __expf(s[mi][ni][3] - mx1);
            sm0 += s[mi][ni][0] + s[mi][ni][1];
            sm1 += s[mi][ni][2] + s[mi][ni][3];
        }
        sm0 += __shfl_xor_sync(0xffffffffu, sm0, 1);
        sm0 += __shfl_xor_sync(0xffffffffu, sm0, 2);
        sm1 += __shfl_xor_sync(0xffffffffu, sm1, 1);
        sm1 += __shfl_xor_sync(0xffffffffu, sm1, 2);
        float i0 = 1.f / sm0, i1 = 1.f / sm1;
        #pragma unroll
        for (int ni = 0; ni < 8; ni++) {
            s[mi][ni][0] *= i0; s[mi][ni][1] *= i0;
            s[mi][ni][2] *= i1; s[mi][ni][3] *= i1;
        }
    }

    // O = P V (P 2-term fp16 from registers)
    float o[2][8][4];
    #pragma unroll
    for (int i = 0; i < 2; i++)
        #pragma unroll
        for (int j = 0; j < 8; j++)
            #pragma unroll
            for (int p = 0; p < 4; p++) o[i][j][p] = 0.f;

    #pragma unroll
    for (int kc = 0; kc < 4; kc++) {
        u32 pah[2][4], pal[2][4], bvh[8][2];
        #pragma unroll
        for (int mi = 0; mi < 2; mi++) {
            split_pack(s[mi][2*kc][0],   s[mi][2*kc][1],   pah[mi][0], pal[mi][0]);
            split_pack(s[mi][2*kc][2],   s[mi][2*kc][3],   pah[mi][1], pal[mi][1]);
            split_pack(s[mi][2*kc+1][0], s[mi][2*kc+1][1], pah[mi][2], pal[mi][2]);
            split_pack(s[mi][2*kc+1][2], s[mi][2*kc+1][3], pah[mi][3], pal[mi][3]);
        }
        #pragma unroll
        for (int jj = 0; jj < 4; jj++) {
            int g = lane >> 3;
            int row = (2 * jj + (g >> 1)) * 8 + (lane & 7);
            int chunk = 2 * kc + (g & 1);
            u32 off = swz((u32)(row * 128 + chunk * 16));
            u32 t[4];
            ldsm4(t, sbase + AVH + off);
            bvh[2*jj][0] = t[0]; bvh[2*jj][1] = t[1];
            bvh[2*jj+1][0] = t[2]; bvh[2*jj+1][1] = t[3];
        }
        #pragma unroll
        for (int mi = 0; mi < 2; mi++)
            #pragma unroll
            for (int ni = 0; ni < 8; ni++) {
                mma16816(o[mi][ni], pah[mi], bvh[ni]);
                mma16816(o[mi][ni], pal[mi], bvh[ni]);
            }
    }

    // store O hi fp16 at [B,Nq,Dq]
    #pragma unroll
    for (int mi = 0; mi < 2; mi++)
        #pragma unroll
        for (int ni = 0; ni < 8; ni++) {
            int q = q0 + wid * 32 + mi * 16 + (lane >> 2);
            int col = h * HD + ni * 8 + (lane & 3) * 2;
            size_t a0 = ((size_t)(b * NQ + q)) * DQ + col;
            size_t a1 = ((size_t)(b * NQ + q + 8)) * DQ + col;
            *(u32*)&g_o_h[a0] = pack_h(o[mi][ni][0], o[mi][ni][1]);
            *(u32*)&g_o_h[a1] = pack_h(o[mi][ni][2], o[mi][ni][3]);
        }
}

// ---------------------------------------------------------------------------
// Launch
// ---------------------------------------------------------------------------
extern "C" void kernel_launch(void* const* d_in, const int* in_sizes, int n_in,
                              void* d_out, int out_size)
{
    (void)in_sizes; (void)n_in; (void)out_size;
    const float* feat   = (const float*)d_in[0];
    const float* tokens = (const float*)d_in[1];
    const float* Wq     = (const float*)d_in[2];
    const float* Wkv    = (const float*)d_in[3];
    const float* Wout   = (const float*)d_in[4];
    const float* bout   = (const float*)d_in[5];
    float* outp = (float*)d_out;

    u16 *pqih, *pwqh, *pwkh, *pwoh, *pth, *poh;
    cudaGetSymbolAddress((void**)&pqih, g_qin_h);
    cudaGetSymbolAddress((void**)&pwqh, g_wq_h);
    cudaGetSymbolAddress((void**)&pwkh, g_wkv_h);
    cudaGetSymbolAddress((void**)&pwoh, g_wo_h);
    cudaGetSymbolAddress((void**)&pth,  g_tok_h);
    cudaGetSymbolAddress((void**)&poh,  g_o_h);

    cudaFuncSetAttribute(gemm_mma<1>, cudaFuncAttributeMaxDynamicSharedMemorySize, GSMEM);
    cudaFuncSetAttribute(gemm_mma<2>, cudaFuncAttributeMaxDynamicSharedMemorySize, GSMEM);
    cudaFuncSetAttribute(gemm_mma<3>, cudaFuncAttributeMaxDynamicSharedMemorySize, GSMEM);
    cudaFuncSetAttribute(attn_tc,     cudaFuncAttributeMaxDynamicSharedMemorySize, ASMEM);

    rope_table<<<(NQ*32 + 255)/256, 256>>>();

    conv_T<<<dim3(NQ/32, DQ/32, BATCH), dim3(32, 8)>>>(
        feat, pqih, DQ, NQ, (size_t)DQ*NQ, (size_t)NQ*DQ);
    conv_T<<<dim3(DQ/32, DQ/32, 1), dim3(32, 8)>>>(Wq,   pwqh, DQ,  DQ,   0, 0);
    conv_T<<<dim3(DKV2/32, DKV/32, 1), dim3(32, 8)>>>(Wkv, pwkh, DKV, DKV2, 0, 0);
    conv_T<<<dim3(DQ/32, DQ/32, 1), dim3(32, 8)>>>(Wout, pwoh, DQ,  DQ,   0, 0);
    conv_lin<<<(NKV*DKV + 255)/256, 256>>>(tokens, pth, NKV*DKV);

    // kv = tokens @ Wkv -> RoPE'd K hi + transposed V hi
    gemm_mma<3><<<dim3(DKV2/128, NKV/128, 1), 256, GSMEM>>>(
        pth, pwkh, nullptr, nullptr, nullptr, DKV, 0, 0);

    // q = q_in @ Wq -> RoPE'd q hi/lo
    gemm_mma<2><<<dim3(DQ/128, NQ/128, BATCH), 256, GSMEM>>>(
        pqih, pwqh, nullptr, nullptr, nullptr, DQ, (size_t)NQ*DQ, 0);

    // attention (tensor cores)
    attn_tc<<<dim3(NQ/128, NH, BATCH), 128, ASMEM>>>();

    // out[d,q] = feat + (o @ Wout)^T + bout ; A = WoutT hi, B = o hi
    gemm_mma<1><<<dim3(NQ/128, DQ/128, BATCH), 256, GSMEM>>>(
        pwoh, poh, outp, feat, bout, DQ, 0, (size_t)NQ*DQ);
}

// round 7
// speedup vs baseline: 8.1872x; 1.0480x over previous
#include <cuda_runtime.h>
#include <cuda_fp16.h>
#include <math.h>

// Problem constants
#define BATCH 16
#define DQ    768
#define NQ    1024
#define NT    64
#define DKV   384
#define NH    12
#define HD    64
#define NKV   (BATCH*NT)
#define DKV2  (2*DQ)

#define NEG_L2B_32 (-0.41524101186091903f)   // -log2(10000)/32

typedef unsigned short u16;
typedef unsigned int   u32;

// ---------------------------------------------------------------------------
// Scratch (device globals)
// ---------------------------------------------------------------------------
__device__ __align__(16) u16 g_qin_h[(size_t)BATCH*NQ*DQ];  // feat^T hi fp16
__device__ __align__(16) u16 g_qr_h [(size_t)BATCH*NQ*DQ];  // rope'd q hi [B,Nq,Dq]
__device__ __align__(16) u16 g_k_h  [(size_t)BATCH*NH*NT*HD];  // rope'd K hi [b,h,t,hd]
__device__ __align__(16) u16 g_vT_h [(size_t)BATCH*NH*HD*NT];  // V^T hi [b,h,hd,t]
__device__ __align__(16) u16 g_o_h  [(size_t)BATCH*NQ*DQ];  // attn out hi [B,Nq,Dq]
__device__ __align__(16) u16 g_wq_h [DQ*DQ];                // WqT hi
__device__ __align__(16) u16 g_wkv_h[DKV2*DKV];             // WkvT hi
__device__ __align__(16) u16 g_wo_h [DQ*DQ];                // WoutT hi
__device__ __align__(16) u16 g_tok_h[NKV*DKV];              // tokens hi
__device__ __align__(16) float2 g_cs[NQ*32];                // (cos, sin)

// ---------------------------------------------------------------------------
// Helpers (base-ISA only)
// ---------------------------------------------------------------------------
__device__ __forceinline__ u32 smem_u32(const void* p) {
    u32 a;
    asm("{ .reg .u64 t; cvta.to.shared.u64 t, %1; cvt.u32.u64 %0, t; }" : "=r"(a) : "l"(p));
    return a;
}
__device__ __forceinline__ u32 swz(u32 o) { return o ^ ((o >> 3) & 0x70); }

__device__ __forceinline__ void cpa16(u32 s, const void* g) {
    asm volatile("cp.async.cg.shared.global [%0], [%1], 16;" :: "r"(s), "l"(g) : "memory");
}
#define CP_COMMIT() asm volatile("cp.async.commit_group;" ::: "memory")
#define CP_WAIT(n)  asm volatile("cp.async.wait_group %0;" :: "n"(n) : "memory")

__device__ __forceinline__ void ldsm4(u32* r, u32 a) {
    asm volatile("ldmatrix.sync.aligned.m8n8.x4.shared.b16 {%0,%1,%2,%3}, [%4];"
                 : "=r"(r[0]), "=r"(r[1]), "=r"(r[2]), "=r"(r[3]) : "r"(a));
}
__device__ __forceinline__ void mma16816(float* c, const u32* a, const u32* b) {
    asm volatile(
        "mma.sync.aligned.m16n8k16.row.col.f32.f16.f16.f32 "
        "{%0,%1,%2,%3}, {%4,%5,%6,%7}, {%8,%9}, {%0,%1,%2,%3};"
        : "+f"(c[0]), "+f"(c[1]), "+f"(c[2]), "+f"(c[3])
        : "r"(a[0]), "r"(a[1]), "r"(a[2]), "r"(a[3]), "r"(b[0]), "r"(b[1]));
}

__device__ __forceinline__ u16 f16h(float v) {
    __half h = __float2half_rn(v);
    return *reinterpret_cast<u16*>(&h);
}
__device__ __forceinline__ u32 pack_h(float a, float b) {
    __half2 h = __float22half2_rn(make_float2(a, b));
    return *reinterpret_cast<u32*>(&h);
}
// pack two floats to hi half2 + lo-residual half2
__device__ __forceinline__ void split_pack(float a, float b, u32& ph, u32& pl) {
    __half2 h = __float22half2_rn(make_float2(a, b));
    float2 hf = __half22float2(h);
    __half2 l = __float22half2_rn(make_float2(a - hf.x, b - hf.y));
    ph = *reinterpret_cast<u32*>(&h);
    pl = *reinterpret_cast<u32*>(&l);
}

// ---------------------------------------------------------------------------
// Fused small-prep kernel: Wq/Wkv/Wout transposed fp16, tokens fp16, rope table
// Block ranges: [0,576) Wq | [576,1152) Wkv | [1152,1728) Wout |
//               [1728,2112) tokens | [2112,2240) rope
// ---------------------------------------------------------------------------
__device__ __forceinline__ void convT_tile(const float* __restrict__ in,
                                           u16* __restrict__ oh,
                                           int R, int C, int bx, int by,
                                           float (*t)[33])
{
    int txx = threadIdx.x & 31, tyy = threadIdx.x >> 5;   // 32 x 8
    int x = bx * 32 + txx;
    int y0 = by * 32 + tyy;
    #pragma unroll
    for (int i = 0; i < 32; i += 8)
        t[tyy + i][txx] = in[(size_t)(y0 + i) * C + x];
    __syncthreads();
    int orow0 = bx * 32 + tyy;
    int ocol  = by * 32 + txx;
    #pragma unroll
    for (int i = 0; i < 32; i += 8)
        oh[(size_t)(orow0 + i) * R + ocol] = f16h(t[txx][tyy + i]);
}

__global__ void __launch_bounds__(256)
conv_small(const float* __restrict__ Wq, const float* __restrict__ Wkv,
           const float* __restrict__ Wout, const float* __restrict__ tok)
{
    __shared__ float t[32][33];
    int bid = blockIdx.x;
    if (bid < 576) {
        convT_tile(Wq, g_wq_h, DQ, DQ, bid % 24, bid / 24, t);
    } else if (bid < 1152) {
        int i = bid - 576;
        convT_tile(Wkv, g_wkv_h, DKV, DKV2, i % 48, i / 48, t);
    } else if (bid < 1728) {
        int i = bid - 1152;
        convT_tile(Wout, g_wo_h, DQ, DQ, i % 24, i / 24, t);
    } else if (bid < 2112) {
        int base = (bid - 1728) * 1024 + threadIdx.x * 4;
        float4 v = *(const float4*)(tok + base);
        *(u32*)&g_tok_h[base]     = pack_h(v.x, v.y);
        *(u32*)&g_tok_h[base + 2] = pack_h(v.z, v.w);
    } else {
        int idx = (bid - 2112) * 256 + threadIdx.x;
        int pos = idx >> 5, i = idx & 31;
        float inv = exp2f((float)i * NEG_L2B_32);
        float sn, cs;
        sincosf((float)pos * inv, &sn, &cs);
        g_cs[idx] = make_float2(cs, sn);
    }
}

// feat: [B][Dq][Nq] fp32 -> g_qin_h [B][Nq][Dq] fp16
__global__ void __launch_bounds__(256)
conv_feat(const float* __restrict__ in)
{
    __shared__ float t[32][33];
    const float* ib = in + (size_t)blockIdx.z * DQ * NQ;
    int x = blockIdx.x * 32 + (threadIdx.x & 31);
    int y0 = blockIdx.y * 32 + (threadIdx.x >> 5);
    #pragma unroll
    for (int i = 0; i < 32; i += 8)
        t[(threadIdx.x >> 5) + i][threadIdx.x & 31] = ib[(size_t)(y0 + i) * NQ + x];
    __syncthreads();
    int orow0 = blockIdx.x * 32 + (threadIdx.x >> 5);
    int ocol  = blockIdx.y * 32 + (threadIdx.x & 31);
    u16* ob = g_qin_h + (size_t)blockIdx.z * NQ * DQ;
    #pragma unroll
    for (int i = 0; i < 32; i += 8)
        ob[(size_t)(orow0 + i) * DQ + ocol] = f16h(t[threadIdx.x & 31][(threadIdx.x >> 5) + i]);
}

// ---------------------------------------------------------------------------
// Pure fp16 1-pass GEMM: C[m,n] = sum_k A[m,k]*B[n,k], K-major fp16 operands.
// 128x128 tile, BK=64, 8 warps (4m x 2n -> warp 32m x 64n), 3-stage, 2 CTA/SM.
// MODE 1: C[(bz*DQ+m)*NQ+n] = acc + Feat[..] + Bias[m]          (out proj)
// MODE 2: RoPE(m, n%64) -> g_qr_h at [(bz*NQ+m)*DQ+n]           (q proj)
// MODE 3: n<768: RoPE K hi -> g_k[b,h,t,hd]; n>=768: V^T hi     (kv proj)
// ---------------------------------------------------------------------------
#define BK 64
#define STG 32768
#define AH_O 0
#define BH_O 16384
#define GSMEM (3*STG)

template<int MODE>
__global__ void __launch_bounds__(256, 2)
gemm_mma(const u16* __restrict__ Ah, const u16* __restrict__ Bh,
         float* __restrict__ C, const float* __restrict__ Feat,
         const float* __restrict__ Bias, int K, size_t sA, size_t sB)
{
    extern __shared__ char smdyn[];
    const u32 sbase = smem_u32(smdyn);
    const int tid  = threadIdx.x;
    const int lane = tid & 31;
    const int wid  = tid >> 5;
    const int wm   = (wid & 3) * 32;
    const int wn   = (wid >> 2) * 64;
    const int m0 = blockIdx.y * 128;
    const int n0 = blockIdx.x * 128;
    const int bz = blockIdx.z;
    const u16* Ahb = Ah + (size_t)bz * sA;
    const u16* Bhb = Bh + (size_t)bz * sB;

    float acc[2][8][4];
    #pragma unroll
    for (int i = 0; i < 2; i++)
        #pragma unroll
        for (int j = 0; j < 8; j++)
            #pragma unroll
            for (int p = 0; p < 4; p++) acc[i][j][p] = 0.f;

    const int KT = K / BK;

    #define LOAD_STAGE(kt, slot) do {                                           \
        u32 so_ = sbase + (u32)(slot) * STG;                                    \
        int k0_ = (kt) * BK;                                                    \
        _Pragma("unroll")                                                       \
        for (int i_ = 0; i_ < 4; i_++) {                                        \
            int chunk_ = i_ * 256 + tid;                                        \
            int row_ = chunk_ >> 3, c_ = chunk_ & 7;                            \
            u32 off_ = swz((u32)(row_ * 128 + c_ * 16));                        \
            size_t ga_ = (size_t)(m0 + row_) * K + k0_ + c_ * 8;                \
            size_t gb_ = (size_t)(n0 + row_) * K + k0_ + c_ * 8;                \
            cpa16(so_ + AH_O + off_, Ahb + ga_);                                \
            cpa16(so_ + BH_O + off_, Bhb + gb_);                                \
        }                                                                       \
    } while (0)

    LOAD_STAGE(0, 0);
    CP_COMMIT();
    if (KT > 1) { LOAD_STAGE(1, 1); CP_COMMIT(); }

    int slot = 0;
    for (int kt = 0; kt < KT; kt++) {
        if (kt + 1 < KT) CP_WAIT(1); else CP_WAIT(0);
        __syncthreads();
        if (kt + 2 < KT) {
            int ns = slot + 2; if (ns >= 3) ns -= 3;
            LOAD_STAGE(kt + 2, ns);
            CP_COMMIT();
        }
        const u32 sa = sbase + (u32)slot * STG;
        #pragma unroll
        for (int ks = 0; ks < 4; ks++) {
            u32 ahf[2][4], bhf[8][2];
            #pragma unroll
            for (int mi = 0; mi < 2; mi++) {
                int row = wm + mi * 16 + (lane & 15);
                int chunk = 2 * ks + (lane >> 4);
                u32 off = swz((u32)(row * 128 + chunk * 16));
                ldsm4(ahf[mi], sa + AH_O + off);
            }
            #pragma unroll
            for (int jj = 0; jj < 4; jj++) {
                int g = lane >> 3;
                int row = wn + (2 * jj + (g >> 1)) * 8 + (lane & 7);
                int chunk = 2 * ks + (g & 1);
                u32 off = swz((u32)(row * 128 + chunk * 16));
                u32 t[4];
                ldsm4(t, sa + BH_O + off);
                bhf[2*jj][0] = t[0]; bhf[2*jj][1] = t[1];
                bhf[2*jj+1][0] = t[2]; bhf[2*jj+1][1] = t[3];
            }
            #pragma unroll
            for (int mi = 0; mi < 2; mi++)
                #pragma unroll
                for (int ni = 0; ni < 8; ni++)
                    mma16816(acc[mi][ni], ahf[mi], bhf[ni]);
        }
        __syncthreads();
        slot++; if (slot >= 3) slot = 0;
    }

    // ---- epilogues ----
    if (MODE == 1) {
        #pragma unroll
        for (int mi = 0; mi < 2; mi++)
            #pragma unroll
            for (int ni = 0; ni < 8; ni++) {
                int m = m0 + wm + mi * 16 + (lane >> 2);
                int n = n0 + wn + ni * 8 + (lane & 3) * 2;
                const float* c = acc[mi][ni];
                size_t a0 = ((size_t)bz * DQ + m) * NQ + n;
                size_t a1 = ((size_t)bz * DQ + m + 8) * NQ + n;
                float b0 = Bias[m], b1 = Bias[m + 8];
                float2 f0 = *(const float2*)&Feat[a0];
                float2 f1 = *(const float2*)&Feat[a1];
                *(float2*)&C[a0] = make_float2(c[0] + f0.x + b0, c[1] + f0.y + b0);
                *(float2*)&C[a1] = make_float2(c[2] + f1.x + b1, c[3] + f1.y + b1);
            }
    } else if (MODE == 2) {
        #pragma unroll
        for (int mi = 0; mi < 2; mi++)
            #pragma unroll
            for (int ni = 0; ni < 4; ni++)
                #pragma unroll
                for (int half = 0; half < 2; half++) {
                    int m = m0 + wm + mi * 16 + (lane >> 2) + half * 8;
                    int i0 = ni * 8 + (lane & 3) * 2;       // i_loc in [0,32)
                    float2 cs0 = g_cs[m * 32 + i0];
                    float2 cs1 = g_cs[m * 32 + i0 + 1];
                    float x1a = acc[mi][ni][half*2],   x2a = acc[mi][ni+4][half*2];
                    float x1b = acc[mi][ni][half*2+1], x2b = acc[mi][ni+4][half*2+1];
                    float y1a = x1a * cs0.x - x2a * cs0.y;
                    float y2a = x2a * cs0.x + x1a * cs0.y;
                    float y1b = x1b * cs1.x - x2b * cs1.y;
                    float y2b = x2b * cs1.x + x1b * cs1.y;
                    int n = n0 + wn + i0;
                    size_t base = ((size_t)bz * NQ + m) * DQ;
                    *(u32*)&g_qr_h[base + n]      = pack_h(y1a, y1b);
                    *(u32*)&g_qr_h[base + n + 32] = pack_h(y2a, y2b);
                }
    } else { // MODE 3 : kv
        if (n0 + wn < DQ) {
            // K half with RoPE (hi only)
            #pragma unroll
            for (int mi = 0; mi < 2; mi++)
                #pragma unroll
                for (int ni = 0; ni < 4; ni++)
                    #pragma unroll
                    for (int half = 0; half < 2; half++) {
                        int m = m0 + wm + mi * 16 + (lane >> 2) + half * 8;
                        int bb = m >> 6, t = m & 63;
                        int n = n0 + wn + ni * 8 + (lane & 3) * 2;
                        int h = n >> 6;
                        int i0 = n & 63;                    // < 32
                        float2 cs0 = g_cs[t * 32 + i0];
                        float2 cs1 = g_cs[t * 32 + i0 + 1];
                        float x1a = acc[mi][ni][half*2],   x2a = acc[mi][ni+4][half*2];
                        float x1b = acc[mi][ni][half*2+1], x2b = acc[mi][ni+4][half*2+1];
                        float y1a = x1a * cs0.x - x2a * cs0.y;
                        float y2a = x2a * cs0.x + x1a * cs0.y;
                        float y1b = x1b * cs1.x - x2b * cs1.y;
                        float y2b = x2b * cs1.x + x1b * cs1.y;
                        size_t base = (((size_t)bb * NH + h) * NT + t) * HD;
                        *(u32*)&g_k_h[base + i0]      = pack_h(y1a, y1b);
                        *(u32*)&g_k_h[base + i0 + 32] = pack_h(y2a, y2b);
                    }
        } else {
            // V half, store transposed [b,h,hd,t] (hi only)
            #pragma unroll
            for (int mi = 0; mi < 2; mi++)
                #pragma unroll
                for (int ni = 0; ni < 8; ni++)
                    #pragma unroll
                    for (int p = 0; p < 4; p++) {
                        int m = m0 + wm + mi * 16 + (lane >> 2) + (p >> 1) * 8;
                        int bb = m >> 6, t = m & 63;
                        int n = n0 + wn + ni * 8 + (lane & 3) * 2 + (p & 1);
                        int h = (n - DQ) >> 6;
                        int hd = n & 63;
                        size_t o = (((size_t)bb * NH + h) * HD + hd) * NT + t;
                        g_vT_h[o] = f16h(acc[mi][ni][p]);
                    }
        }
    }
    #undef LOAD_STAGE
}

// ---------------------------------------------------------------------------
// Tensor-core attention: grid (NQ/256, NH, BATCH), 256 threads (8 warps).
// Block = 256 q-rows x 1 head. Q single fp16, P 2-term fp16 in registers.
// ---------------------------------------------------------------------------
#define AQH 0
#define AKH 32768
#define AVH 40960
#define ASMEM 49152

__global__ void __launch_bounds__(256)
attn_tc()
{
    extern __shared__ char smdyn[];
    const u32 sbase = smem_u32(smdyn);
    const int tid  = threadIdx.x;
    const int lane = tid & 31;
    const int wid  = tid >> 5;
    const int q0 = blockIdx.x * 256;
    const int h  = blockIdx.y;
    const int b  = blockIdx.z;

    {
        const u16* qh = g_qr_h + ((size_t)(b * NQ + q0)) * DQ + h * HD;
        #pragma unroll
        for (int i = 0; i < 8; i++) {
            int c = i * 256 + tid;
            int row = c >> 3, cc = c & 7;
            u32 off = swz((u32)(row * 128 + cc * 16));
            cpa16(sbase + AQH + off, qh + (size_t)row * DQ + cc * 8);
        }
        size_t kvb = ((size_t)b * NH + h) * (NT * HD);
        #pragma unroll
        for (int i = 0; i < 2; i++) {
            int c = i * 256 + tid;
            int row = c >> 3, cc = c & 7;
            u32 off = swz((u32)(row * 128 + cc * 16));
            cpa16(sbase + AKH + off, g_k_h  + kvb + row * 64 + cc * 8);
            cpa16(sbase + AVH + off, g_vT_h + kvb + row * 64 + cc * 8);
        }
        CP_COMMIT();
        CP_WAIT(0);
        __syncthreads();
    }

    // S = Q K^T (Q single-term)
    float s[2][8][4];
    #pragma unroll
    for (int i = 0; i < 2; i++)
        #pragma unroll
        for (int j = 0; j < 8; j++)
            #pragma unroll
            for (int p = 0; p < 4; p++) s[i][j][p] = 0.f;

    #pragma unroll
    for (int ks = 0; ks < 4; ks++) {
        u32 aqh[2][4], bkh[8][2];
        #pragma unroll
        for (int mi = 0; mi < 2; mi++) {
            int row = wid * 32 + mi * 16 + (lane & 15);
            int chunk = 2 * ks + (lane >> 4);
            u32 off = swz((u32)(row * 128 + chunk * 16));
            ldsm4(aqh[mi], sbase + AQH + off);
        }
        #pragma unroll
        for (int jj = 0; jj < 4; jj++) {
            int g = lane >> 3;
            int row = (2 * jj + (g >> 1)) * 8 + (lane & 7);
            int chunk = 2 * ks + (g & 1);
            u32 off = swz((u32)(row * 128 + chunk * 16));
            u32 t[4];
            ldsm4(t, sbase + AKH + off);
            bkh[2*jj][0] = t[0]; bkh[2*jj][1] = t[1];
            bkh[2*jj+1][0] = t[2]; bkh[2*jj+1][1] = t[3];
        }
        #pragma unroll
        for (int mi = 0; mi < 2; mi++)
            #pragma unroll
            for (int ni = 0; ni < 8; ni++)
                mma16816(s[mi][ni], aqh[mi], bkh[ni]);
    }

    // softmax (scale 1/8)
    #pragma unroll
    for (int mi = 0; mi < 2; mi++) {
        float mx0 = -1e30f, mx1 = -1e30f;
        #pragma unroll
        for (int ni = 0; ni < 8; ni++) {
            #pragma unroll
            for (int p = 0; p < 4; p++) s[mi][ni][p] *= 0.125f;
            mx0 = fmaxf(mx0, fmaxf(s[mi][ni][0], s[mi][ni][1]));
            mx1 = fmaxf(mx1, fmaxf(s[mi][ni][2], s[mi][ni][3]));
        }
        mx0 = fmaxf(mx0, __shfl_xor_sync(0xffffffffu, mx0, 1));
        mx0 = fmaxf(mx0, __shfl_xor_sync(0xffffffffu, mx0, 2));
        mx1 = fmaxf(mx1, __shfl_xor_sync(0xffffffffu, mx1, 1));
        mx1 = fmaxf(mx1, __shfl_xor_sync(0xffffffffu, mx1, 2));
        float sm0 = 0.f, sm1 = 0.f;
        #pragma unroll
        for (int ni = 0; ni < 8; ni++) {
            s[mi][ni][0] = __expf(s[mi][ni][0] - mx0);
            s[mi][ni][1] = __expf(s[mi][ni][1] - mx0);
            s[mi][ni][2] = __expf(s[mi][ni][2] - mx1);
            s[mi][ni][3] = __expf(s[mi][ni][3] - mx1);
            sm0 += s[mi][ni][0] + s[mi][ni][1];
            sm1 += s[mi][ni][2] + s[mi][ni][3];
        }
        sm0 += __shfl_xor_sync(0xffffffffu, sm0, 1);
        sm0 += __shfl_xor_sync(0xffffffffu, sm0, 2);
        sm1 += __shfl_xor_sync(0xffffffffu, sm1, 1);
        sm1 += __shfl_xor_sync(0xffffffffu, sm1, 2);
        float i0 = 1.f / sm0, i1 = 1.f / sm1;
        #pragma unroll
        for (int ni = 0; ni < 8; ni++) {
            s[mi][ni][0] *= i0; s[mi][ni][1] *= i0;
            s[mi][ni][2] *= i1; s[mi][ni][3] *= i1;
        }
    }

    // O = P V (P 2-term fp16 from registers)
    float o[2][8][4];
    #pragma unroll
    for (int i = 0; i < 2; i++)
        #pragma unroll
        for (int j = 0; j < 8; j++)
            #pragma unroll
            for (int p = 0; p < 4; p++) o[i][j][p] = 0.f;

    #pragma unroll
    for (int kc = 0; kc < 4; kc++) {
        u32 pah[2][4], pal[2][4], bvh[8][2];
        #pragma unroll
        for (int mi = 0; mi < 2; mi++) {
            split_pack(s[mi][2*kc][0],   s[mi][2*kc][1],   pah[mi][0], pal[mi][0]);
            split_pack(s[mi][2*kc][2],   s[mi][2*kc][3],   pah[mi][1], pal[mi][1]);
            split_pack(s[mi][2*kc+1][0], s[mi][2*kc+1][1], pah[mi][2], pal[mi][2]);
            split_pack(s[mi][2*kc+1][2], s[mi][2*kc+1][3], pah[mi][3], pal[mi][3]);
        }
        #pragma unroll
        for (int jj = 0; jj < 4; jj++) {
            int g = lane >> 3;
            int row = (2 * jj + (g >> 1)) * 8 + (lane & 7);
            int chunk = 2 * kc + (g & 1);
            u32 off = swz((u32)(row * 128 + chunk * 16));
            u32 t[4];
            ldsm4(t, sbase + AVH + off);
            bvh[2*jj][0] = t[0]; bvh[2*jj][1] = t[1];
            bvh[2*jj+1][0] = t[2]; bvh[2*jj+1][1] = t[3];
        }
        #pragma unroll
        for (int mi = 0; mi < 2; mi++)
            #pragma unroll
            for (int ni = 0; ni < 8; ni++) {
                mma16816(o[mi][ni], pah[mi], bvh[ni]);
                mma16816(o[mi][ni], pal[mi], bvh[ni]);
            }
    }

    // store O hi fp16 at [B,Nq,Dq]
    #pragma unroll
    for (int mi = 0; mi < 2; mi++)
        #pragma unroll
        for (int ni = 0; ni < 8; ni++) {
            int q = q0 + wid * 32 + mi * 16 + (lane >> 2);
            int col = h * HD + ni * 8 + (lane & 3) * 2;
            size_t a0 = ((size_t)(b * NQ + q)) * DQ + col;
            size_t a1 = ((size_t)(b * NQ + q + 8)) * DQ + col;
            *(u32*)&g_o_h[a0] = pack_h(o[mi][ni][0], o[mi][ni][1]);
            *(u32*)&g_o_h[a1] = pack_h(o[mi][ni][2], o[mi][ni][3]);
        }
}

// ---------------------------------------------------------------------------
// Launch
// ---------------------------------------------------------------------------
extern "C" void kernel_launch(void* const* d_in, const int* in_sizes, int n_in,
                              void* d_out, int out_size)
{
    (void)in_sizes; (void)n_in; (void)out_size;
    const float* feat   = (const float*)d_in[0];
    const float* tokens = (const float*)d_in[1];
    const float* Wq     = (const float*)d_in[2];
    const float* Wkv    = (const float*)d_in[3];
    const float* Wout   = (const float*)d_in[4];
    const float* bout   = (const float*)d_in[5];
    float* outp = (float*)d_out;

    u16 *pqih, *pwqh, *pwkh, *pwoh, *pth, *poh;
    cudaGetSymbolAddress((void**)&pqih, g_qin_h);
    cudaGetSymbolAddress((void**)&pwqh, g_wq_h);
    cudaGetSymbolAddress((void**)&pwkh, g_wkv_h);
    cudaGetSymbolAddress((void**)&pwoh, g_wo_h);
    cudaGetSymbolAddress((void**)&pth,  g_tok_h);
    cudaGetSymbolAddress((void**)&poh,  g_o_h);

    cudaFuncSetAttribute(gemm_mma<1>, cudaFuncAttributeMaxDynamicSharedMemorySize, GSMEM);
    cudaFuncSetAttribute(gemm_mma<2>, cudaFuncAttributeMaxDynamicSharedMemorySize, GSMEM);
    cudaFuncSetAttribute(gemm_mma<3>, cudaFuncAttributeMaxDynamicSharedMemorySize, GSMEM);
    cudaFuncSetAttribute(attn_tc,     cudaFuncAttributeMaxDynamicSharedMemorySize, ASMEM);

    // all small preprocessing in one launch
    conv_small<<<2240, 256>>>(Wq, Wkv, Wout, tokens);
    // feat transpose+convert
    conv_feat<<<dim3(NQ/32, DQ/32, BATCH), 256>>>(feat);

    // kv = tokens @ Wkv -> RoPE'd K hi + transposed V hi
    gemm_mma<3><<<dim3(DKV2/128, NKV/128, 1), 256, GSMEM>>>(
        pth, pwkh, nullptr, nullptr, nullptr, DKV, 0, 0);

    // q = q_in @ Wq -> RoPE'd q hi
    gemm_mma<2><<<dim3(DQ/128, NQ/128, BATCH), 256, GSMEM>>>(
        pqih, pwqh, nullptr, nullptr, nullptr, DQ, (size_t)NQ*DQ, 0);

    // attention (tensor cores)
    attn_tc<<<dim3(NQ/256, NH, BATCH), 256, ASMEM>>>();

    // out[d,q] = feat + (o @ Wout)^T + bout ; A = WoutT hi, B = o hi
    gemm_mma<1><<<dim3(NQ/128, DQ/128, BATCH), 256, GSMEM>>>(
        pwoh, poh, outp, feat, bout, DQ, 0, (size_t)NQ*DQ);
}

// round 8
// speedup vs baseline: 8.9265x; 1.0903x over previous
#include <cuda_runtime.h>
#include <cuda_fp16.h>
#include <math.h>

// Problem constants
#define BATCH 16
#define DQ    768
#define NQ    1024
#define NT    64
#define DKV   384
#define NH    12
#define HD    64
#define NKV   (BATCH*NT)
#define DKV2  (2*DQ)

#define NEG_L2B_32 (-0.41524101186091903f)   // -log2(10000)/32

typedef unsigned short u16;
typedef unsigned int   u32;

// ---------------------------------------------------------------------------
// Scratch (device globals)
// ---------------------------------------------------------------------------
__device__ __align__(16) u16 g_qin_h[(size_t)BATCH*NQ*DQ];     // feat^T hi fp16
__device__ __align__(16) u16 g_k_h  [(size_t)BATCH*NH*NT*HD];  // rope'd K hi [b,h,t,hd]
__device__ __align__(16) u16 g_vT_h [(size_t)BATCH*NH*HD*NT];  // V^T hi [b,h,hd,t]
__device__ __align__(16) u16 g_o_h  [(size_t)BATCH*NQ*DQ];     // attn out hi [B,Nq,Dq]
__device__ __align__(16) u16 g_wq_h [DQ*DQ];                   // WqT hi
__device__ __align__(16) u16 g_wkv_h[DKV2*DKV];                // WkvT hi
__device__ __align__(16) u16 g_wo_h [DQ*DQ];                   // WoutT hi
__device__ __align__(16) u16 g_tok_h[NKV*DKV];                 // tokens hi
__device__ __align__(16) float2 g_cs[NQ*32];                   // (cos, sin)

// ---------------------------------------------------------------------------
// Helpers (base-ISA only)
// ---------------------------------------------------------------------------
__device__ __forceinline__ u32 smem_u32(const void* p) {
    u32 a;
    asm("{ .reg .u64 t; cvta.to.shared.u64 t, %1; cvt.u32.u64 %0, t; }" : "=r"(a) : "l"(p));
    return a;
}
__device__ __forceinline__ u32 swz(u32 o) { return o ^ ((o >> 3) & 0x70); }

__device__ __forceinline__ void cpa16(u32 s, const void* g) {
    asm volatile("cp.async.cg.shared.global [%0], [%1], 16;" :: "r"(s), "l"(g) : "memory");
}
#define CP_COMMIT() asm volatile("cp.async.commit_group;" ::: "memory")
#define CP_WAIT(n)  asm volatile("cp.async.wait_group %0;" :: "n"(n) : "memory")

__device__ __forceinline__ void ldsm4(u32* r, u32 a) {
    asm volatile("ldmatrix.sync.aligned.m8n8.x4.shared.b16 {%0,%1,%2,%3}, [%4];"
                 : "=r"(r[0]), "=r"(r[1]), "=r"(r[2]), "=r"(r[3]) : "r"(a));
}
__device__ __forceinline__ void mma16816(float* c, const u32* a, const u32* b) {
    asm volatile(
        "mma.sync.aligned.m16n8k16.row.col.f32.f16.f16.f32 "
        "{%0,%1,%2,%3}, {%4,%5,%6,%7}, {%8,%9}, {%0,%1,%2,%3};"
        : "+f"(c[0]), "+f"(c[1]), "+f"(c[2]), "+f"(c[3])
        : "r"(a[0]), "r"(a[1]), "r"(a[2]), "r"(a[3]), "r"(b[0]), "r"(b[1]));
}

__device__ __forceinline__ u16 f16h(float v) {
    __half h = __float2half_rn(v);
    return *reinterpret_cast<u16*>(&h);
}
__device__ __forceinline__ u32 pack_h(float a, float b) {
    __half2 h = __float22half2_rn(make_float2(a, b));
    return *reinterpret_cast<u32*>(&h);
}
__device__ __forceinline__ void split_pack(float a, float b, u32& ph, u32& pl) {
    __half2 h = __float22half2_rn(make_float2(a, b));
    float2 hf = __half22float2(h);
    __half2 l = __float22half2_rn(make_float2(a - hf.x, b - hf.y));
    ph = *reinterpret_cast<u32*>(&h);
    pl = *reinterpret_cast<u32*>(&l);
}

// ---------------------------------------------------------------------------
// Fused small-prep kernel (weights T + tokens + rope table)
// ---------------------------------------------------------------------------
__device__ __forceinline__ void convT_tile(const float* __restrict__ in,
                                           u16* __restrict__ oh,
                                           int R, int C, int bx, int by,
                                           float (*t)[33])
{
    int txx = threadIdx.x & 31, tyy = threadIdx.x >> 5;
    int x = bx * 32 + txx;
    int y0 = by * 32 + tyy;
    #pragma unroll
    for (int i = 0; i < 32; i += 8)
        t[tyy + i][txx] = in[(size_t)(y0 + i) * C + x];
    __syncthreads();
    int orow0 = bx * 32 + tyy;
    int ocol  = by * 32 + txx;
    #pragma unroll
    for (int i = 0; i < 32; i += 8)
        oh[(size_t)(orow0 + i) * R + ocol] = f16h(t[txx][tyy + i]);
}

__global__ void __launch_bounds__(256)
conv_small(const float* __restrict__ Wq, const float* __restrict__ Wkv,
           const float* __restrict__ Wout, const float* __restrict__ tok)
{
    __shared__ float t[32][33];
    int bid = blockIdx.x;
    if (bid < 576) {
        convT_tile(Wq, g_wq_h, DQ, DQ, bid % 24, bid / 24, t);
    } else if (bid < 1152) {
        int i = bid - 576;
        convT_tile(Wkv, g_wkv_h, DKV, DKV2, i % 48, i / 48, t);
    } else if (bid < 1728) {
        int i = bid - 1152;
        convT_tile(Wout, g_wo_h, DQ, DQ, i % 24, i / 24, t);
    } else if (bid < 2112) {
        int base = (bid - 1728) * 1024 + threadIdx.x * 4;
        float4 v = *(const float4*)(tok + base);
        *(u32*)&g_tok_h[base]     = pack_h(v.x, v.y);
        *(u32*)&g_tok_h[base + 2] = pack_h(v.z, v.w);
    } else {
        int idx = (bid - 2112) * 256 + threadIdx.x;
        int pos = idx >> 5, i = idx & 31;
        float inv = exp2f((float)i * NEG_L2B_32);
        float sn, cs;
        sincosf((float)pos * inv, &sn, &cs);
        g_cs[idx] = make_float2(cs, sn);
    }
}

// feat: [B][Dq][Nq] fp32 -> g_qin_h [B][Nq][Dq] fp16
__global__ void __launch_bounds__(256)
conv_feat(const float* __restrict__ in)
{
    __shared__ float t[32][33];
    const float* ib = in + (size_t)blockIdx.z * DQ * NQ;
    int x = blockIdx.x * 32 + (threadIdx.x & 31);
    int y0 = blockIdx.y * 32 + (threadIdx.x >> 5);
    #pragma unroll
    for (int i = 0; i < 32; i += 8)
        t[(threadIdx.x >> 5) + i][threadIdx.x & 31] = ib[(size_t)(y0 + i) * NQ + x];
    __syncthreads();
    int orow0 = blockIdx.x * 32 + (threadIdx.x >> 5);
    int ocol  = blockIdx.y * 32 + (threadIdx.x & 31);
    u16* ob = g_qin_h + (size_t)blockIdx.z * NQ * DQ;
    #pragma unroll
    for (int i = 0; i < 32; i += 8)
        ob[(size_t)(orow0 + i) * DQ + ocol] = f16h(t[threadIdx.x & 31][(threadIdx.x >> 5) + i]);
}

// ---------------------------------------------------------------------------
// fp16 GEMM: C[m,n] = sum_k A[m,k]*B[n,k]; 128x128 tile, BK=64, 8 warps,
// 3-stage cp.async, 2 CTA/SM, single __syncthreads per k-tile.
// MODE 1: out proj: C[(bz*DQ+m)*NQ+n] = acc + Feat + Bias[m]
// MODE 2: q proj + RoPE + FUSED ATTENTION -> g_o_h
// MODE 3: kv proj: RoPE K -> g_k ; V^T -> g_vT
// ---------------------------------------------------------------------------
#define BK 64
#define STG 32768
#define AH_O 0
#define BH_O 16384
#define GSMEM (3*STG)
// fused-attention smem overlay (within the 96KB stages, reused post-mainloop)
#define QOFF 0
#define KOFF 32768
#define VOFF 49152

template<int MODE>
__global__ void __launch_bounds__(256, 2)
gemm_mma(const u16* __restrict__ Ah, const u16* __restrict__ Bh,
         float* __restrict__ C, const float* __restrict__ Feat,
         const float* __restrict__ Bias, int K, size_t sA, size_t sB)
{
    extern __shared__ char smdyn[];
    const u32 sbase = smem_u32(smdyn);
    const int tid  = threadIdx.x;
    const int lane = tid & 31;
    const int wid  = tid >> 5;
    const int wm   = (wid & 3) * 32;
    const int wn   = (wid >> 2) * 64;
    const int m0 = blockIdx.y * 128;
    const int n0 = blockIdx.x * 128;
    const int bz = blockIdx.z;
    const u16* Ahb = Ah + (size_t)bz * sA;
    const u16* Bhb = Bh + (size_t)bz * sB;

    float acc[2][8][4];
    #pragma unroll
    for (int i = 0; i < 2; i++)
        #pragma unroll
        for (int j = 0; j < 8; j++)
            #pragma unroll
            for (int p = 0; p < 4; p++) acc[i][j][p] = 0.f;

    const int KT = K / BK;

    #define LOAD_STAGE(kt, slot) do {                                           \
        u32 so_ = sbase + (u32)(slot) * STG;                                    \
        int k0_ = (kt) * BK;                                                    \
        _Pragma("unroll")                                                       \
        for (int i_ = 0; i_ < 4; i_++) {                                        \
            int chunk_ = i_ * 256 + tid;                                        \
            int row_ = chunk_ >> 3, c_ = chunk_ & 7;                            \
            u32 off_ = swz((u32)(row_ * 128 + c_ * 16));                        \
            size_t ga_ = (size_t)(m0 + row_) * K + k0_ + c_ * 8;                \
            size_t gb_ = (size_t)(n0 + row_) * K + k0_ + c_ * 8;                \
            cpa16(so_ + AH_O + off_, Ahb + ga_);                                \
            cpa16(so_ + BH_O + off_, Bhb + gb_);                                \
        }                                                                       \
    } while (0)

    LOAD_STAGE(0, 0);
    CP_COMMIT();
    if (KT > 1) { LOAD_STAGE(1, 1); CP_COMMIT(); }

    int slot = 0;
    for (int kt = 0; kt < KT; kt++) {
        if (kt + 1 < KT) CP_WAIT(1); else CP_WAIT(0);
        __syncthreads();
        if (kt + 2 < KT) {
            int ns = slot + 2; if (ns >= 3) ns -= 3;
            LOAD_STAGE(kt + 2, ns);
            CP_COMMIT();
        }
        const u32 sa = sbase + (u32)slot * STG;
        #pragma unroll
        for (int ks = 0; ks < 4; ks++) {
            u32 ahf[2][4], bhf[8][2];
            #pragma unroll
            for (int mi = 0; mi < 2; mi++) {
                int row = wm + mi * 16 + (lane & 15);
                int chunk = 2 * ks + (lane >> 4);
                u32 off = swz((u32)(row * 128 + chunk * 16));
                ldsm4(ahf[mi], sa + AH_O + off);
            }
            #pragma unroll
            for (int jj = 0; jj < 4; jj++) {
                int g = lane >> 3;
                int row = wn + (2 * jj + (g >> 1)) * 8 + (lane & 7);
                int chunk = 2 * ks + (g & 1);
                u32 off = swz((u32)(row * 128 + chunk * 16));
                u32 t[4];
                ldsm4(t, sa + BH_O + off);
                bhf[2*jj][0] = t[0]; bhf[2*jj][1] = t[1];
                bhf[2*jj+1][0] = t[2]; bhf[2*jj+1][1] = t[3];
            }
            #pragma unroll
            for (int mi = 0; mi < 2; mi++)
                #pragma unroll
                for (int ni = 0; ni < 8; ni++)
                    mma16816(acc[mi][ni], ahf[mi], bhf[ni]);
        }
        slot++; if (slot >= 3) slot = 0;
    }

    // ---- epilogues ----
    if (MODE == 1) {
        #pragma unroll
        for (int mi = 0; mi < 2; mi++)
            #pragma unroll
            for (int ni = 0; ni < 8; ni++) {
                int m = m0 + wm + mi * 16 + (lane >> 2);
                int n = n0 + wn + ni * 8 + (lane & 3) * 2;
                const float* c = acc[mi][ni];
                size_t a0 = ((size_t)bz * DQ + m) * NQ + n;
                size_t a1 = ((size_t)bz * DQ + m + 8) * NQ + n;
                float b0 = Bias[m], b1 = Bias[m + 8];
                float2 f0 = *(const float2*)&Feat[a0];
                float2 f1 = *(const float2*)&Feat[a1];
                *(float2*)&C[a0] = make_float2(c[0] + f0.x + b0, c[1] + f0.y + b0);
                *(float2*)&C[a1] = make_float2(c[2] + f1.x + b1, c[3] + f1.y + b1);
            }
    } else if (MODE == 2) {
        // ===== fused RoPE + attention =====
        __syncthreads();   // all ldsm of final stage done before smem reuse

        // issue K/V loads for this CTA's two heads (overlap with RoPE below)
        const int hbase = n0 >> 6;
        {
            size_t kvb = ((size_t)bz * NH + hbase) * (NT * HD);
            #pragma unroll
            for (int i = 0; i < 4; i++) {
                int c = i * 256 + tid;          // 0..1023
                int hh = c >> 9;                // head 0/1
                int r  = (c >> 3) & 63;
                int cc = c & 7;
                u32 off = (u32)hh * 8192 + swz((u32)(r * 128 + cc * 16));
                cpa16(sbase + KOFF + off, g_k_h  + kvb + (size_t)hh * (NT*HD) + r * HD + cc * 8);
                cpa16(sbase + VOFF + off, g_vT_h + kvb + (size_t)hh * (NT*HD) + r * HD + cc * 8);
            }
            CP_COMMIT();
        }

        // RoPE acc -> q fp16 into smem (per-head 16KB tiles)
        const int hh_w = wid >> 2;              // warp's head (from wn)
        const u32 qbase = sbase + QOFF + (u32)hh_w * 16384;
        #pragma unroll
        for (int mi = 0; mi < 2; mi++)
            #pragma unroll
            for (int ni = 0; ni < 4; ni++)
                #pragma unroll
                for (int half = 0; half < 2; half++) {
                    int m_loc = wm + mi * 16 + (lane >> 2) + half * 8;
                    int m = m0 + m_loc;
                    int i0 = ni * 8 + (lane & 3) * 2;   // [0,32)
                    float2 cs0 = g_cs[m * 32 + i0];
                    float2 cs1 = g_cs[m * 32 + i0 + 1];
                    float x1a = acc[mi][ni][half*2],   x2a = acc[mi][ni+4][half*2];
                    float x1b = acc[mi][ni][half*2+1], x2b = acc[mi][ni+4][half*2+1];
                    float y1a = x1a * cs0.x - x2a * cs0.y;
                    float y2a = x2a * cs0.x + x1a * cs0.y;
                    float y1b = x1b * cs1.x - x2b * cs1.y;
                    float y2b = x2b * cs1.x + x1b * cs1.y;
                    asm volatile("st.shared.u32 [%0], %1;" ::
                        "r"(qbase + swz((u32)(m_loc * 128 + i0 * 2))), "r"(pack_h(y1a, y1b)));
                    asm volatile("st.shared.u32 [%0], %1;" ::
                        "r"(qbase + swz((u32)(m_loc * 128 + (i0 + 32) * 2))), "r"(pack_h(y2a, y2b)));
                }
        CP_WAIT(0);
        __syncthreads();

        // attention: warp = 32 q-rows x 64 keys, head hh_w
        const u32 kbase = sbase + KOFF + (u32)hh_w * 8192;
        const u32 vbase = sbase + VOFF + (u32)hh_w * 8192;
        const int qw = (wid & 3) * 32;

        float s[2][8][4];
        #pragma unroll
        for (int i = 0; i < 2; i++)
            #pragma unroll
            for (int j = 0; j < 8; j++)
                #pragma unroll
                for (int p = 0; p < 4; p++) s[i][j][p] = 0.f;

        #pragma unroll
        for (int ks = 0; ks < 4; ks++) {
            u32 aq[2][4], bk[8][2];
            #pragma unroll
            for (int mi = 0; mi < 2; mi++) {
                int row = qw + mi * 16 + (lane & 15);
                int chunk = 2 * ks + (lane >> 4);
                ldsm4(aq[mi], qbase + swz((u32)(row * 128 + chunk * 16)));
            }
            #pragma unroll
            for (int jj = 0; jj < 4; jj++) {
                int g = lane >> 3;
                int row = (2 * jj + (g >> 1)) * 8 + (lane & 7);
                int chunk = 2 * ks + (g & 1);
                u32 t[4];
                ldsm4(t, kbase + swz((u32)(row * 128 + chunk * 16)));
                bk[2*jj][0] = t[0]; bk[2*jj][1] = t[1];
                bk[2*jj+1][0] = t[2]; bk[2*jj+1][1] = t[3];
            }
            #pragma unroll
            for (int mi = 0; mi < 2; mi++)
                #pragma unroll
                for (int ni = 0; ni < 8; ni++)
                    mma16816(s[mi][ni], aq[mi], bk[ni]);
        }

        // softmax (scale 1/8)
        #pragma unroll
        for (int mi = 0; mi < 2; mi++) {
            float mx0 = -1e30f, mx1 = -1e30f;
            #pragma unroll
            for (int ni = 0; ni < 8; ni++) {
                #pragma unroll
                for (int p = 0; p < 4; p++) s[mi][ni][p] *= 0.125f;
                mx0 = fmaxf(mx0, fmaxf(s[mi][ni][0], s[mi][ni][1]));
                mx1 = fmaxf(mx1, fmaxf(s[mi][ni][2], s[mi][ni][3]));
            }
            mx0 = fmaxf(mx0, __shfl_xor_sync(0xffffffffu, mx0, 1));
            mx0 = fmaxf(mx0, __shfl_xor_sync(0xffffffffu, mx0, 2));
            mx1 = fmaxf(mx1, __shfl_xor_sync(0xffffffffu, mx1, 1));
            mx1 = fmaxf(mx1, __shfl_xor_sync(0xffffffffu, mx1, 2));
            float sm0 = 0.f, sm1 = 0.f;
            #pragma unroll
            for (int ni = 0; ni < 8; ni++) {
                s[mi][ni][0] = __expf(s[mi][ni][0] - mx0);
                s[mi][ni][1] = __expf(s[mi][ni][1] - mx0);
                s[mi][ni][2] = __expf(s[mi][ni][2] - mx1);
                s[mi][ni][3] = __expf(s[mi][ni][3] - mx1);
                sm0 += s[mi][ni][0] + s[mi][ni][1];
                sm1 += s[mi][ni][2] + s[mi][ni][3];
            }
            sm0 += __shfl_xor_sync(0xffffffffu, sm0, 1);
            sm0 += __shfl_xor_sync(0xffffffffu, sm0, 2);
            sm1 += __shfl_xor_sync(0xffffffffu, sm1, 1);
            sm1 += __shfl_xor_sync(0xffffffffu, sm1, 2);
            float i0 = 1.f / sm0, i1 = 1.f / sm1;
            #pragma unroll
            for (int ni = 0; ni < 8; ni++) {
                s[mi][ni][0] *= i0; s[mi][ni][1] *= i0;
                s[mi][ni][2] *= i1; s[mi][ni][3] *= i1;
            }
        }

        // O = P V (P 2-term fp16 in registers)
        float o[2][8][4];
        #pragma unroll
        for (int i = 0; i < 2; i++)
            #pragma unroll
            for (int j = 0; j < 8; j++)
                #pragma unroll
                for (int p = 0; p < 4; p++) o[i][j][p] = 0.f;

        #pragma unroll
        for (int kc = 0; kc < 4; kc++) {
            u32 pah[2][4], pal[2][4], bv[8][2];
            #pragma unroll
            for (int mi = 0; mi < 2; mi++) {
                split_pack(s[mi][2*kc][0],   s[mi][2*kc][1],   pah[mi][0], pal[mi][0]);
                split_pack(s[mi][2*kc][2],   s[mi][2*kc][3],   pah[mi][1], pal[mi][1]);
                split_pack(s[mi][2*kc+1][0], s[mi][2*kc+1][1], pah[mi][2], pal[mi][2]);
                split_pack(s[mi][2*kc+1][2], s[mi][2*kc+1][3], pah[mi][3], pal[mi][3]);
            }
            #pragma unroll
            for (int jj = 0; jj < 4; jj++) {
                int g = lane >> 3;
                int row = (2 * jj + (g >> 1)) * 8 + (lane & 7);
                int chunk = 2 * kc + (g & 1);
                u32 t[4];
                ldsm4(t, vbase + swz((u32)(row * 128 + chunk * 16)));
                bv[2*jj][0] = t[0]; bv[2*jj][1] = t[1];
                bv[2*jj+1][0] = t[2]; bv[2*jj+1][1] = t[3];
            }
            #pragma unroll
            for (int mi = 0; mi < 2; mi++)
                #pragma unroll
                for (int ni = 0; ni < 8; ni++) {
                    mma16816(o[mi][ni], pah[mi], bv[ni]);
                    mma16816(o[mi][ni], pal[mi], bv[ni]);
                }
        }

        // store O hi fp16 at [B,Nq,Dq]
        #pragma unroll
        for (int mi = 0; mi < 2; mi++)
            #pragma unroll
            for (int ni = 0; ni < 8; ni++) {
                int q = m0 + qw + mi * 16 + (lane >> 2);
                int col = n0 + hh_w * 64 + ni * 8 + (lane & 3) * 2;
                size_t a0 = ((size_t)(bz * NQ + q)) * DQ + col;
                size_t a1 = ((size_t)(bz * NQ + q + 8)) * DQ + col;
                *(u32*)&g_o_h[a0] = pack_h(o[mi][ni][0], o[mi][ni][1]);
                *(u32*)&g_o_h[a1] = pack_h(o[mi][ni][2], o[mi][ni][3]);
            }
    } else { // MODE 3 : kv
        if (n0 + wn < DQ) {
            // K half with RoPE (hi only)
            #pragma unroll
            for (int mi = 0; mi < 2; mi++)
                #pragma unroll
                for (int ni = 0; ni < 4; ni++)
                    #pragma unroll
                    for (int half = 0; half < 2; half++) {
                        int m = m0 + wm + mi * 16 + (lane >> 2) + half * 8;
                        int bb = m >> 6, t = m & 63;
                        int n = n0 + wn + ni * 8 + (lane & 3) * 2;
                        int h = n >> 6;
                        int i0 = n & 63;                    // < 32
                        float2 cs0 = g_cs[t * 32 + i0];
                        float2 cs1 = g_cs[t * 32 + i0 + 1];
                        float x1a = acc[mi][ni][half*2],   x2a = acc[mi][ni+4][half*2];
                        float x1b = acc[mi][ni][half*2+1], x2b = acc[mi][ni+4][half*2+1];
                        float y1a = x1a * cs0.x - x2a * cs0.y;
                        float y2a = x2a * cs0.x + x1a * cs0.y;
                        float y1b = x1b * cs1.x - x2b * cs1.y;
                        float y2b = x2b * cs1.x + x1b * cs1.y;
                        size_t base = (((size_t)bb * NH + h) * NT + t) * HD;
                        *(u32*)&g_k_h[base + i0]      = pack_h(y1a, y1b);
                        *(u32*)&g_k_h[base + i0 + 32] = pack_h(y2a, y2b);
                    }
        } else {
            // V half, store transposed [b,h,hd,t] (hi only)
            #pragma unroll
            for (int mi = 0; mi < 2; mi++)
                #pragma unroll
                for (int ni = 0; ni < 8; ni++)
                    #pragma unroll
                    for (int p = 0; p < 4; p++) {
                        int m = m0 + wm + mi * 16 + (lane >> 2) + (p >> 1) * 8;
                        int bb = m >> 6, t = m & 63;
                        int n = n0 + wn + ni * 8 + (lane & 3) * 2 + (p & 1);
                        int h = (n - DQ) >> 6;
                        int hd = n & 63;
                        size_t o = (((size_t)bb * NH + h) * HD + hd) * NT + t;
                        g_vT_h[o] = f16h(acc[mi][ni][p]);
                    }
        }
    }
    #undef LOAD_STAGE
}

// ---------------------------------------------------------------------------
// Launch
// ---------------------------------------------------------------------------
extern "C" void kernel_launch(void* const* d_in, const int* in_sizes, int n_in,
                              void* d_out, int out_size)
{
    (void)in_sizes; (void)n_in; (void)out_size;
    const float* feat   = (const float*)d_in[0];
    const float* tokens = (const float*)d_in[1];
    const float* Wq     = (const float*)d_in[2];
    const float* Wkv    = (const float*)d_in[3];
    const float* Wout   = (const float*)d_in[4];
    const float* bout   = (const float*)d_in[5];
    float* outp = (float*)d_out;

    u16 *pqih, *pwqh, *pwkh, *pwoh, *pth, *poh;
    cudaGetSymbolAddress((void**)&pqih, g_qin_h);
    cudaGetSymbolAddress((void**)&pwqh, g_wq_h);
    cudaGetSymbolAddress((void**)&pwkh, g_wkv_h);
    cudaGetSymbolAddress((void**)&pwoh, g_wo_h);
    cudaGetSymbolAddress((void**)&pth,  g_tok_h);
    cudaGetSymbolAddress((void**)&poh,  g_o_h);

    cudaFuncSetAttribute(gemm_mma<1>, cudaFuncAttributeMaxDynamicSharedMemorySize, GSMEM);
    cudaFuncSetAttribute(gemm_mma<2>, cudaFuncAttributeMaxDynamicSharedMemorySize, GSMEM);
    cudaFuncSetAttribute(gemm_mma<3>, cudaFuncAttributeMaxDynamicSharedMemorySize, GSMEM);

    // all small preprocessing in one launch
    conv_small<<<2240, 256>>>(Wq, Wkv, Wout, tokens);
    // feat transpose+convert
    conv_feat<<<dim3(NQ/32, DQ/32, BATCH), 256>>>(feat);

    // kv = tokens @ Wkv -> RoPE'd K hi + transposed V hi
    gemm_mma<3><<<dim3(DKV2/128, NKV/128, 1), 256, GSMEM>>>(
        pth, pwkh, nullptr, nullptr, nullptr, DKV, 0, 0);

    // q = q_in @ Wq -> RoPE + fused attention -> g_o_h
    gemm_mma<2><<<dim3(DQ/128, NQ/128, BATCH), 256, GSMEM>>>(
        pqih, pwqh, nullptr, nullptr, nullptr, DQ, (size_t)NQ*DQ, 0);

    // out[d,q] = feat + (o @ Wout)^T + bout ; A = WoutT hi, B = o hi
    gemm_mma<1><<<dim3(NQ/128, DQ/128, BATCH), 256, GSMEM>>>(
        pwoh, poh, outp, feat, bout, DQ, 0, (size_t)NQ*DQ);
}